// round 9
// baseline (speedup 1.0000x reference)
#include <cuda_runtime.h>
#include <cuda_fp16.h>
#include <mma.h>
#include <math.h>
#include <limits.h>

using namespace nvcuda;

#define DIM 128
#define NH 4
#define MAXN 50048
#define MAXE 800032
#define MAXDEG 96
#define SCANB 256

// ---------------- scratch (static device globals; no allocation) ----------------
__device__ __half g_hsA[MAXN * DIM];
__device__ __half g_hsB[MAXN * DIM];
__device__ __half g_Wh[4 * DIM * DIM];
__device__ float g_hfood[MAXN * DIM];
__device__ float g_hnut[MAXN * DIM];
__device__ float g_asA[MAXN * NH];
__device__ float g_adA[MAXN * NH];
__device__ float g_asB[MAXN * NH];
__device__ float g_adB[MAXN * NH];
__device__ float g_uv[4096];
__device__ int   g_deg[2 * MAXN];     // zero-init; re-zeroed by sortZK epilogue
__device__ int   g_cur[2 * MAXN];
__device__ int   g_bsum[2 * 256];
__device__ int   g_offA[MAXN + 1];
__device__ int   g_offB[MAXN + 1];
__device__ int   g_srcA[MAXE];
__device__ int   g_srcB[MAXE];

// ---------------- CSR build ----------------
__global__ void histK(const int* __restrict__ dst, int* __restrict__ deg, int E) {
    int i = blockIdx.x * blockDim.x + threadIdx.x;
    int stride = gridDim.x * blockDim.x;
    for (; i < E; i += stride) atomicAdd(&deg[dst[i]], 1);
}

__global__ void scanSumK(const int* __restrict__ deg, int* __restrict__ bsum, int n) {
    __shared__ int wsum[8];
    int t = threadIdx.x;
    int i = blockIdx.x * SCANB + t;
    int v = (i < n) ? deg[i] : 0;
    #pragma unroll
    for (int o = 16; o > 0; o >>= 1) v += __shfl_down_sync(0xffffffffu, v, o);
    if ((t & 31) == 0) wsum[t >> 5] = v;
    __syncthreads();
    if (t == 0) {
        int s = 0;
        #pragma unroll
        for (int w = 0; w < 8; w++) s += wsum[w];
        bsum[blockIdx.x] = s;
    }
}

// per-block scan + apply, with inline top-level scan of block sums
__global__ void scanApplyK(const int* __restrict__ deg, const int* __restrict__ bsum,
                           int* __restrict__ off, int* __restrict__ cur, int n) {
    __shared__ int wsum[8];
    __shared__ int shBase;
    int t = threadIdx.x;
    int lane = t & 31, wid = t >> 5;
    if (wid == 0) {
        int s = 0;
        for (int j = lane; j < blockIdx.x; j += 32) s += bsum[j];
        #pragma unroll
        for (int o = 16; o > 0; o >>= 1) s += __shfl_down_sync(0xffffffffu, s, o);
        if (lane == 0) shBase = s;
    }
    int i = blockIdx.x * SCANB + t;
    int v = (i < n) ? deg[i] : 0;
    int incl = v;
    #pragma unroll
    for (int o = 1; o < 32; o <<= 1) {
        int x = __shfl_up_sync(0xffffffffu, incl, o);
        if (lane >= o) incl += x;
    }
    if (lane == 31) wsum[wid] = incl;
    __syncthreads();
    if (wid == 0 && lane < 8) {
        int w = wsum[lane];
        int wi = w;
        #pragma unroll
        for (int o = 1; o < 8; o <<= 1) {
            int x = __shfl_up_sync(0xffu, wi, o);
            if (lane >= o) wi += x;
        }
        wsum[lane] = wi - w;
    }
    __syncthreads();
    int excl = incl - v + wsum[wid] + shBase;
    if (i < n) {
        off[i] = excl;
        cur[i] = excl;
        if (i == n - 1) off[n] = excl + v;
    }
}

__global__ void fillK(const int* __restrict__ ei, int* __restrict__ cur,
                      int* __restrict__ csrc, int E) {
    int i = blockIdx.x * blockDim.x + threadIdx.x;
    int stride = gridDim.x * blockDim.x;
    for (; i < E; i += stride) {
        int pos = atomicAdd(&cur[ei[E + i]], 1);
        csrc[pos] = ei[i];
    }
}

__global__ void __launch_bounds__(256)
sortZK(const int* __restrict__ off, int* __restrict__ csrc, int n,
       int* __restrict__ deg) {
    for (int i = blockIdx.x * blockDim.x + threadIdx.x; i < n;
         i += gridDim.x * blockDim.x) deg[i] = 0;

    int w = (blockIdx.x * blockDim.x + threadIdx.x) >> 5;
    int lane = threadIdx.x & 31;
    if (w >= n) return;
    int beg = off[w];
    int cnt = off[w + 1] - beg;
    if (cnt <= 1) return;
    if (cnt <= 32) {
        int v0 = (lane < cnt) ? csrc[beg + lane] : INT_MAX;
        #pragma unroll
        for (int size = 2; size <= 32; size <<= 1) {
            #pragma unroll
            for (int stride = size >> 1; stride > 0; stride >>= 1) {
                int p0 = __shfl_xor_sync(0xffffffffu, v0, stride);
                bool up0 = (size == 32) ? true : ((lane & size) == 0);
                bool lower = ((lane & stride) == 0);
                v0 = (lower == up0) ? min(v0, p0) : max(v0, p0);
            }
        }
        if (lane < cnt) csrc[beg + lane] = v0;
    } else if (cnt <= 64) {
        int v0 = (lane < cnt) ? csrc[beg + lane] : INT_MAX;
        int v1 = (32 + lane < cnt) ? csrc[beg + 32 + lane] : INT_MAX;
        #pragma unroll
        for (int size = 2; size <= 64; size <<= 1) {
            #pragma unroll
            for (int stride = size >> 1; stride > 0; stride >>= 1) {
                if (stride == 32) {
                    int lo = min(v0, v1), hi = max(v0, v1);
                    v0 = lo; v1 = hi;
                } else {
                    int p0 = __shfl_xor_sync(0xffffffffu, v0, stride);
                    int p1 = __shfl_xor_sync(0xffffffffu, v1, stride);
                    bool up0, up1;
                    if (size == 64)      { up0 = true; up1 = true; }
                    else if (size == 32) { up0 = true; up1 = false; }
                    else { up0 = ((lane & size) == 0); up1 = up0; }
                    bool lower = ((lane & stride) == 0);
                    v0 = (lower == up0) ? min(v0, p0) : max(v0, p0);
                    v1 = (lower == up1) ? min(v1, p1) : max(v1, p1);
                }
            }
        }
        if (lane < cnt) csrc[beg + lane] = v0;
        if (32 + lane < cnt) csrc[beg + 32 + lane] = v1;
    } else if (lane == 0) {
        int end = beg + cnt;
        for (int i = beg + 1; i < end; i++) {
            int key = csrc[i];
            int j = i - 1;
            while (j >= beg && csrc[j] > key) { csrc[j + 1] = csrc[j]; j--; }
            csrc[j + 1] = key;
        }
    }
}

// ---------------- folded attention vectors ----------------
__global__ void uvK(const float* __restrict__ WsrcFN, const float* __restrict__ WdstFN,
                    const float* __restrict__ aSrcFN, const float* __restrict__ aDstFN,
                    const float* __restrict__ WsrcNF, const float* __restrict__ WdstNF,
                    const float* __restrict__ aSrcNF, const float* __restrict__ aDstNF,
                    float* __restrict__ uv) {
    int t = blockIdx.x * blockDim.x + threadIdx.x;
    if (t >= 4096) return;
    int h = t & 3;
    int k = (t >> 2) & 127;
    int sv = (t >> 9) & 1;
    int rel = (t >> 10) & 1;
    int l = (t >> 11) & 1;
    const float* W;
    const float* att;
    if (rel == 0) { W = sv ? WdstFN : WsrcFN; att = sv ? aDstFN : aSrcFN; }
    else          { W = sv ? WdstNF : WsrcNF; att = sv ? aDstNF : aSrcNF; }
    W += l * DIM * DIM;
    att += l * NH * 32;
    float sum = 0.f;
    #pragma unroll 8
    for (int c = 0; c < 32; c++)
        sum += W[k * DIM + h * 32 + c] * att[h * 32 + c];
    uv[t] = sum;
}

// ---------------- fp16 weight conversion ----------------
__global__ void convWK(const float* __restrict__ WsrcFN, const float* __restrict__ WsrcNF,
                       __half* __restrict__ Wh) {
    int i = blockIdx.x * blockDim.x + threadIdx.x;
    if (i >= 4 * DIM * DIM) return;
    int rel = i >> 15;
    int rest = i & 32767;
    const float* W = rel ? WsrcNF : WsrcFN;
    Wh[i] = __float2half(W[rest]);
}

// ---------------- alpha projections ----------------
__global__ void alphaK(const float4* __restrict__ x, const float* __restrict__ vmat,
                       const float* __restrict__ umat, float4* __restrict__ asOut,
                       float4* __restrict__ adOut, int n) {
    __shared__ float sv[512];
    __shared__ float su[512];
    int t = threadIdx.x;
    for (int i = t; i < 512; i += blockDim.x) { sv[i] = vmat[i]; su[i] = umat[i]; }
    __syncthreads();
    int warp = (blockIdx.x * blockDim.x + t) >> 5;
    int lane = t & 31;
    if (warp >= n) return;
    float4 xv = x[warp * 32 + lane];
    float xj[4] = {xv.x, xv.y, xv.z, xv.w};
    float pa[4] = {0, 0, 0, 0}, pd[4] = {0, 0, 0, 0};
    int j0 = lane * 4;
    #pragma unroll
    for (int j = 0; j < 4; j++) {
        #pragma unroll
        for (int h = 0; h < 4; h++) {
            pa[h] += xj[j] * sv[(j0 + j) * 4 + h];
            pd[h] += xj[j] * su[(j0 + j) * 4 + h];
        }
    }
    #pragma unroll
    for (int o = 16; o > 0; o >>= 1) {
        #pragma unroll
        for (int h = 0; h < 4; h++) {
            pa[h] += __shfl_down_sync(0xffffffffu, pa[h], o);
            pd[h] += __shfl_down_sync(0xffffffffu, pd[h], o);
        }
    }
    if (lane == 0) {
        asOut[warp] = make_float4(pa[0], pa[1], pa[2], pa[3]);
        adOut[warp] = make_float4(pd[0], pd[1], pd[2], pd[3]);
    }
}

// ---------------- tensor-core GEMM with grid-stride tile loop ----------------
__global__ void __launch_bounds__(256)
gemmTC(const float* __restrict__ A, const __half* __restrict__ Wh,
       __half* __restrict__ C, int M, int numTiles) {
    __shared__ __half bsm[128 * 136];
    __shared__ union {
        __half a[64 * 136];
        float c[64 * 132];
    } sm;
    int t = threadIdx.x;

    {
        int r = t >> 1;
        int c0 = (t & 1) * 64;
        const uint4* src = (const uint4*)(Wh + r * DIM + c0);
        uint4* dst = (uint4*)(&bsm[r * 136 + c0]);
        #pragma unroll
        for (int i = 0; i < 8; i++) dst[i] = src[i];
    }

    int warpId = t >> 5;
    int wr = warpId & 3;
    int wc = warpId >> 2;

    for (int tile = blockIdx.x; tile < numTiles; tile += gridDim.x) {
        int rowBase = tile * 64;
        __syncthreads();

        {
            int r = t >> 2;
            int c0 = (t & 3) * 32;
            int gr = rowBase + r;
            const float4* src = (const float4*)(A + (size_t)gr * DIM + c0);
            __half* dst = &sm.a[r * 136 + c0];
            if (gr < M) {
                #pragma unroll
                for (int i = 0; i < 8; i++) {
                    float4 v = src[i];
                    *(__half2*)(dst + i * 4)     = __floats2half2_rn(v.x, v.y);
                    *(__half2*)(dst + i * 4 + 2) = __floats2half2_rn(v.z, v.w);
                }
            } else {
                #pragma unroll
                for (int i = 0; i < 8; i++) {
                    *(__half2*)(dst + i * 4)     = __half2half2(__float2half(0.f));
                    *(__half2*)(dst + i * 4 + 2) = __half2half2(__float2half(0.f));
                }
            }
        }
        __syncthreads();

        wmma::fragment<wmma::accumulator, 16, 16, 16, float> cf[4];
        #pragma unroll
        for (int j = 0; j < 4; j++) wmma::fill_fragment(cf[j], 0.f);

        #pragma unroll
        for (int k0 = 0; k0 < 8; k0++) {
            wmma::fragment<wmma::matrix_a, 16, 16, 16, __half, wmma::row_major> af;
            wmma::load_matrix_sync(af, &sm.a[(wr * 16) * 136 + k0 * 16], 136);
            #pragma unroll
            for (int j = 0; j < 4; j++) {
                wmma::fragment<wmma::matrix_b, 16, 16, 16, __half, wmma::row_major> bf;
                wmma::load_matrix_sync(bf, &bsm[(k0 * 16) * 136 + wc * 64 + j * 16], 136);
                wmma::mma_sync(cf[j], af, bf, cf[j]);
            }
        }
        __syncthreads();

        #pragma unroll
        for (int j = 0; j < 4; j++)
            wmma::store_matrix_sync(&sm.c[(wr * 16) * 132 + wc * 64 + j * 16], cf[j], 132,
                                    wmma::mem_row_major);
        __syncthreads();

        {
            int r = t >> 2;
            int c0 = (t & 3) * 32;
            int gr = rowBase + r;
            if (gr < M) {
                const float* src = &sm.c[r * 132 + c0];
                __half2* dst = (__half2*)(C + (size_t)gr * DIM + c0);
                #pragma unroll
                for (int i = 0; i < 16; i++)
                    dst[i] = __floats2half2_rn(src[2 * i], src[2 * i + 1]);
            }
        }
    }
}

// ---------------- fused softmax-stats + aggregation + bias + ELU ----------------
// Pass 2 is 4-way edge-parallel: 4 subgroups x 8 lanes; each lane covers 16
// channels via TWO uint4 loads (2 x 8 halves); partials combined via shfl_xor(8,16).
__global__ void __launch_bounds__(256)
fusedAggK(const int* __restrict__ off, const int* __restrict__ csrc,
          const float4* __restrict__ as4, const float* __restrict__ as1,
          const float4* __restrict__ ad,
          const __half* __restrict__ hs, const float* __restrict__ bias,
          float* __restrict__ out, int n) {
    __shared__ float see[8][MAXDEG][4];
    __shared__ int ssrc[8][MAXDEG];
    int w = threadIdx.x >> 5;
    int lane = threadIdx.x & 31;
    int d = blockIdx.x * 8 + w;
    if (d >= n) return;

    int beg = off[d], end = off[d + 1];
    int deg = end - beg;
    bool cached = (deg <= MAXDEG);

    float4 adv = ad[d];
    float adh4[4] = {adv.x, adv.y, adv.z, adv.w};
    float m[4] = {-1e30f, -1e30f, -1e30f, -1e30f};
    float s[4] = {0.f, 0.f, 0.f, 0.f};

    // ---- pass 1: per-lane online softmax stats, cache logits + src ----
    for (int i = lane; i < deg; i += 32) {
        int src = csrc[beg + i];
        float4 av = as4[src];
        float ev[4] = {av.x + adh4[0], av.y + adh4[1], av.z + adh4[2], av.w + adh4[3]};
        float ee[4];
        #pragma unroll
        for (int h = 0; h < 4; h++) {
            float e = ev[h] > 0.f ? ev[h] : 0.2f * ev[h];
            ee[h] = e;
            if (e > m[h]) {
                s[h] = s[h] * __expf(m[h] - e) + 1.f;
                m[h] = e;
            } else {
                s[h] += __expf(e - m[h]);
            }
        }
        if (cached) {
            ssrc[w][i] = src;
            *(float4*)(&see[w][i][0]) = make_float4(ee[0], ee[1], ee[2], ee[3]);
        }
    }
    // warp merge of (m, s)
    #pragma unroll
    for (int o = 16; o > 0; o >>= 1) {
        #pragma unroll
        for (int h = 0; h < 4; h++) {
            float om = __shfl_xor_sync(0xffffffffu, m[h], o);
            float os = __shfl_xor_sync(0xffffffffu, s[h], o);
            float nm = fmaxf(m[h], om);
            s[h] = s[h] * __expf(m[h] - nm) + os * __expf(om - nm);
            m[h] = nm;
        }
    }
    float rAll[4];
    #pragma unroll
    for (int h = 0; h < 4; h++) rAll[h] = 1.f / (s[h] + 1e-16f);

    // lane-parallel weight precompute (logits -> final weights in smem)
    if (cached) {
        for (int i = lane; i < deg; i += 32) {
            float4 e4 = *(float4*)(&see[w][i][0]);
            e4.x = __expf(e4.x - m[0]) * rAll[0];
            e4.y = __expf(e4.y - m[1]) * rAll[1];
            e4.z = __expf(e4.z - m[2]) * rAll[2];
            e4.w = __expf(e4.w - m[3]) * rAll[3];
            *(float4*)(&see[w][i][0]) = e4;
        }
    }
    __syncwarp();

    // ---- pass 2: 4-way edge-parallel weighted gather ----
    int sub = lane >> 3;      // edge subgroup 0..3
    int cl = lane & 7;        // channel lane: channels [16*cl, 16*cl+16)
    int hh = cl >> 1;         // head for these channels
    float mh = m[hh];
    float rh = rAll[hh];
    float adh = adh4[hh];

    float accv[16];
    #pragma unroll
    for (int k = 0; k < 16; k++) accv[k] = 0.f;

    for (int e = sub; e < deg; e += 4) {
        int src;
        float wgt;
        if (cached) {
            src = ssrc[w][e];
            wgt = see[w][e][hh];
        } else {
            src = csrc[beg + e];
            float a = __ldg(&as1[src * 4 + hh]);
            float ev = a + adh;
            float ee = ev > 0.f ? ev : 0.2f * ev;
            wgt = __expf(ee - mh) * rh;
        }
        // 16 channels = 32 bytes = TWO uint4 loads (8 halves each)
        const uint4* bp = (const uint4*)(hs + (size_t)src * DIM);
        uint4 pv0 = bp[cl * 2];
        uint4 pv1 = bp[cl * 2 + 1];
        const __half2* ph0 = (const __half2*)&pv0;
        const __half2* ph1 = (const __half2*)&pv1;
        #pragma unroll
        for (int k = 0; k < 4; k++) {
            float2 f = __half22float2(ph0[k]);
            accv[2 * k]     += wgt * f.x;
            accv[2 * k + 1] += wgt * f.y;
        }
        #pragma unroll
        for (int k = 0; k < 4; k++) {
            float2 f = __half22float2(ph1[k]);
            accv[8 + 2 * k]     += wgt * f.x;
            accv[8 + 2 * k + 1] += wgt * f.y;
        }
    }
    // combine subgroup partials (lanes differing in bits 3,4)
    #pragma unroll
    for (int k = 0; k < 16; k++) {
        accv[k] += __shfl_xor_sync(0xffffffffu, accv[k], 8);
        accv[k] += __shfl_xor_sync(0xffffffffu, accv[k], 16);
    }

    if (sub == 0) {  // lanes 0..7 write 16 channels each
        const float4* bp = (const float4*)(bias + cl * 16);
        float4* op = (float4*)(out + (size_t)d * DIM + cl * 16);
        #pragma unroll
        for (int q = 0; q < 4; q++) {
            float4 b = bp[q];
            float4 v;
            v.x = accv[4 * q + 0] + b.x;
            v.y = accv[4 * q + 1] + b.y;
            v.z = accv[4 * q + 2] + b.z;
            v.w = accv[4 * q + 3] + b.w;
            v.x = v.x > 0.f ? v.x : expm1f(v.x);
            v.y = v.y > 0.f ? v.y : expm1f(v.y);
            v.z = v.z > 0.f ? v.z : expm1f(v.z);
            v.w = v.w > 0.f ? v.w : expm1f(v.w);
            op[q] = v;
        }
    }
}

// ---------------- driver ----------------
extern "C" void kernel_launch(void* const* d_in, const int* in_sizes, int n_in,
                              void* d_out, int out_size) {
    const float* x_food  = (const float*)d_in[0];
    const float* x_nut   = (const float*)d_in[1];
    const float* WsrcFN  = (const float*)d_in[2];
    const float* WdstFN  = (const float*)d_in[3];
    const float* aSrcFN  = (const float*)d_in[4];
    const float* aDstFN  = (const float*)d_in[5];
    const float* biasFN  = (const float*)d_in[6];
    const float* WsrcNF  = (const float*)d_in[7];
    const float* WdstNF  = (const float*)d_in[8];
    const float* aSrcNF  = (const float*)d_in[9];
    const float* aDstNF  = (const float*)d_in[10];
    const float* biasNF  = (const float*)d_in[11];
    const int*   ei_fn   = (const int*)d_in[12];
    const int*   ei_nf   = (const int*)d_in[13];
    float* out = (float*)d_out;

    int NF = in_sizes[0] / DIM;
    int NN = in_sizes[1] / DIM;
    int E  = in_sizes[12] / 2;

    __half *hsA, *hsB, *Wh;
    float *hfood, *hnut, *asA, *adA, *asB, *adB, *uv;
    int *deg, *cur, *bsum, *offA, *offB, *srcA, *srcB;
    cudaGetSymbolAddress((void**)&hsA, g_hsA);
    cudaGetSymbolAddress((void**)&hsB, g_hsB);
    cudaGetSymbolAddress((void**)&Wh, g_Wh);
    cudaGetSymbolAddress((void**)&hfood, g_hfood);
    cudaGetSymbolAddress((void**)&hnut, g_hnut);
    cudaGetSymbolAddress((void**)&asA, g_asA);
    cudaGetSymbolAddress((void**)&adA, g_adA);
    cudaGetSymbolAddress((void**)&asB, g_asB);
    cudaGetSymbolAddress((void**)&adB, g_adB);
    cudaGetSymbolAddress((void**)&uv, g_uv);
    cudaGetSymbolAddress((void**)&deg, g_deg);
    cudaGetSymbolAddress((void**)&cur, g_cur);
    cudaGetSymbolAddress((void**)&bsum, g_bsum);
    cudaGetSymbolAddress((void**)&offA, g_offA);
    cudaGetSymbolAddress((void**)&offB, g_offB);
    cudaGetSymbolAddress((void**)&srcA, g_srcA);
    cudaGetSymbolAddress((void**)&srcB, g_srcB);

    int* degA = deg;
    int* degB = deg + MAXN;
    int* curA = cur;
    int* curB = cur + MAXN;
    int* bsumA = bsum;
    int* bsumB = bsum + 256;

    int warpBlk_NN = (NN + 7) / 8;
    int warpBlk_NF = (NF + 7) / 8;
    int gemmTiles_NF = (NF + 63) / 64;
    int gemmTiles_NN = (NN + 63) / 64;
    const int GEMM_GRID = 304;
    int scanBlkA = (NN + SCANB - 1) / SCANB;
    int scanBlkB = (NF + SCANB - 1) / SCANB;

    static cudaStream_t s1 = nullptr, s2 = nullptr;
    static cudaEvent_t eR, eUW, eCA, eAl0, eB0, eA0, eAl1, eB1;
    if (!s1) {
        cudaStreamCreateWithFlags(&s1, cudaStreamNonBlocking);
        cudaStreamCreateWithFlags(&s2, cudaStreamNonBlocking);
        cudaEventCreateWithFlags(&eR,   cudaEventDisableTiming);
        cudaEventCreateWithFlags(&eUW,  cudaEventDisableTiming);
        cudaEventCreateWithFlags(&eCA,  cudaEventDisableTiming);
        cudaEventCreateWithFlags(&eAl0, cudaEventDisableTiming);
        cudaEventCreateWithFlags(&eB0,  cudaEventDisableTiming);
        cudaEventCreateWithFlags(&eA0,  cudaEventDisableTiming);
        cudaEventCreateWithFlags(&eAl1, cudaEventDisableTiming);
        cudaEventCreateWithFlags(&eB1,  cudaEventDisableTiming);
    }

    const float* v_fn0 = uv + 0 * 2048 + 0 * 1024 + 0 * 512;
    const float* u_fn0 = uv + 0 * 2048 + 0 * 1024 + 1 * 512;
    const float* v_nf0 = uv + 0 * 2048 + 1 * 1024 + 0 * 512;
    const float* u_nf0 = uv + 0 * 2048 + 1 * 1024 + 1 * 512;
    const float* v_fn1 = uv + 1 * 2048 + 0 * 1024 + 0 * 512;
    const float* u_fn1 = uv + 1 * 2048 + 0 * 1024 + 1 * 512;
    const float* v_nf1 = uv + 1 * 2048 + 1 * 1024 + 0 * 512;
    const float* u_nf1 = uv + 1 * 2048 + 1 * 1024 + 1 * 512;
    const __half* Wh_fn0 = Wh + 0 * DIM * DIM;
    const __half* Wh_fn1 = Wh + 1 * DIM * DIM;
    const __half* Wh_nf0 = Wh + 2 * DIM * DIM;
    const __half* Wh_nf1 = Wh + 3 * DIM * DIM;
    float* out_food = out;
    float* out_nut  = out + (size_t)NF * DIM;

    // ---- fork ----
    cudaEventRecord(eR, 0);
    cudaStreamWaitEvent(s1, eR, 0);
    cudaStreamWaitEvent(s2, eR, 0);

    // S0: weights
    convWK<<<(4 * DIM * DIM + 255) / 256, 256>>>(WsrcFN, WsrcNF, Wh);
    uvK<<<16, 256>>>(WsrcFN, WdstFN, aSrcFN, aDstFN, WsrcNF, WdstNF, aSrcNF, aDstNF, uv);
    cudaEventRecord(eUW, 0);

    // S1: CSR-A
    histK<<<1024, 256, 0, s1>>>(ei_fn + E, degA, E);
    scanSumK<<<scanBlkA, SCANB, 0, s1>>>(degA, bsumA, NN);
    scanApplyK<<<scanBlkA, SCANB, 0, s1>>>(degA, bsumA, offA, curA, NN);
    fillK<<<1024, 256, 0, s1>>>(ei_fn, curA, srcA, E);
    sortZK<<<(NN + 7) / 8, 256, 0, s1>>>(offA, srcA, NN, degA);
    cudaEventRecord(eCA, s1);

    // S2: CSR-B
    histK<<<1024, 256, 0, s2>>>(ei_nf + E, degB, E);
    scanSumK<<<scanBlkB, SCANB, 0, s2>>>(degB, bsumB, NF);
    scanApplyK<<<scanBlkB, SCANB, 0, s2>>>(degB, bsumB, offB, curB, NF);
    fillK<<<1024, 256, 0, s2>>>(ei_nf, curB, srcB, E);
    sortZK<<<(NF + 7) / 8, 256, 0, s2>>>(offB, srcB, NF, degB);

    // S0: layer-0 fn GEMM + alphas
    gemmTC<<<GEMM_GRID, 256>>>(x_food, Wh_fn0, hsA, NF, gemmTiles_NF);
    alphaK<<<warpBlk_NF, 256>>>((const float4*)x_food, v_fn0, u_nf0,
                                (float4*)asA, (float4*)adB, NF);
    alphaK<<<warpBlk_NN, 256>>>((const float4*)x_nut, v_nf0, u_fn0,
                                (float4*)asB, (float4*)adA, NN);
    cudaEventRecord(eAl0, 0);

    // S2: layer-0 nf chain
    cudaStreamWaitEvent(s2, eUW, 0);
    gemmTC<<<GEMM_GRID, 256, 0, s2>>>(x_nut, Wh_nf0, hsB, NN, gemmTiles_NN);
    cudaStreamWaitEvent(s2, eAl0, 0);
    fusedAggK<<<warpBlk_NF, 256, 0, s2>>>(offB, srcB, (const float4*)asB, asB,
                                          (const float4*)adB, hsB, biasNF,
                                          hfood, NF);
    cudaEventRecord(eB0, s2);

    // S0: layer-0 fn agg
    cudaStreamWaitEvent(0, eCA, 0);
    fusedAggK<<<warpBlk_NN, 256>>>(offA, srcA, (const float4*)asA, asA,
                                   (const float4*)adA, hsA, biasFN,
                                   hnut, NN);
    cudaEventRecord(eA0, 0);

    // S0: layer-1
    cudaStreamWaitEvent(0, eB0, 0);
    alphaK<<<warpBlk_NF, 256>>>((const float4*)hfood, v_fn1, u_nf1,
                                (float4*)asA, (float4*)adB, NF);
    alphaK<<<warpBlk_NN, 256>>>((const float4*)hnut, v_nf1, u_fn1,
                                (float4*)asB, (float4*)adA, NN);
    cudaEventRecord(eAl1, 0);
    gemmTC<<<GEMM_GRID, 256>>>(hfood, Wh_fn1, hsA, NF, gemmTiles_NF);
    fusedAggK<<<warpBlk_NN, 256>>>(offA, srcA, (const float4*)asA, asA,
                                   (const float4*)adA, hsA, biasFN + DIM,
                                   out_nut, NN);

    // S2: layer-1 nf chain
    cudaStreamWaitEvent(s2, eA0, 0);
    gemmTC<<<GEMM_GRID, 256, 0, s2>>>(hnut, Wh_nf1, hsB, NN, gemmTiles_NN);
    cudaStreamWaitEvent(s2, eAl1, 0);
    fusedAggK<<<warpBlk_NF, 256, 0, s2>>>(offB, srcB, (const float4*)asB, asB,
                                          (const float4*)adB, hsB, biasNF + DIM,
                                          out_food, NF);
    cudaEventRecord(eB1, s2);

    // ---- join ----
    cudaStreamWaitEvent(0, eB1, 0);
}

// round 10
// speedup vs baseline: 1.0966x; 1.0966x over previous
#include <cuda_runtime.h>
#include <cuda_fp16.h>
#include <mma.h>
#include <math.h>
#include <limits.h>

using namespace nvcuda;

#define DIM 128
#define NH 4
#define MAXN 50048
#define MAXE 800032
#define MAXDEG 96
#define SCANB 256

// ---------------- scratch (static device globals; no allocation) ----------------
__device__ __half g_hsA[MAXN * DIM];
__device__ __half g_hsB[MAXN * DIM];
__device__ __half g_Wh[4 * DIM * DIM];
__device__ float g_hfood[MAXN * DIM];
__device__ float g_hnut[MAXN * DIM];
__device__ float g_asA[MAXN * NH];
__device__ float g_adA[MAXN * NH];
__device__ float g_asB[MAXN * NH];
__device__ float g_adB[MAXN * NH];
__device__ float g_as2A[MAXN * NH];   // layer-1 alphas (separate buffers: no WAR races)
__device__ float g_ad2A[MAXN * NH];
__device__ float g_as2B[MAXN * NH];
__device__ float g_ad2B[MAXN * NH];
__device__ float g_uv[4096];
__device__ int   g_deg[2 * MAXN];     // zero-init; re-zeroed by sortZK epilogue
__device__ int   g_cur[2 * MAXN];
__device__ int   g_bsum[2 * 256];
__device__ int   g_offA[MAXN + 1];
__device__ int   g_offB[MAXN + 1];
__device__ int   g_srcA[MAXE];
__device__ int   g_srcB[MAXE];

// ---------------- CSR build ----------------
__global__ void histK(const int* __restrict__ dst, int* __restrict__ deg, int E) {
    int i = blockIdx.x * blockDim.x + threadIdx.x;
    int stride = gridDim.x * blockDim.x;
    for (; i < E; i += stride) atomicAdd(&deg[dst[i]], 1);
}

__global__ void scanSumK(const int* __restrict__ deg, int* __restrict__ bsum, int n) {
    __shared__ int wsum[8];
    int t = threadIdx.x;
    int i = blockIdx.x * SCANB + t;
    int v = (i < n) ? deg[i] : 0;
    #pragma unroll
    for (int o = 16; o > 0; o >>= 1) v += __shfl_down_sync(0xffffffffu, v, o);
    if ((t & 31) == 0) wsum[t >> 5] = v;
    __syncthreads();
    if (t == 0) {
        int s = 0;
        #pragma unroll
        for (int w = 0; w < 8; w++) s += wsum[w];
        bsum[blockIdx.x] = s;
    }
}

__global__ void scanApplyK(const int* __restrict__ deg, const int* __restrict__ bsum,
                           int* __restrict__ off, int* __restrict__ cur, int n) {
    __shared__ int wsum[8];
    __shared__ int shBase;
    int t = threadIdx.x;
    int lane = t & 31, wid = t >> 5;
    if (wid == 0) {
        int s = 0;
        for (int j = lane; j < blockIdx.x; j += 32) s += bsum[j];
        #pragma unroll
        for (int o = 16; o > 0; o >>= 1) s += __shfl_down_sync(0xffffffffu, s, o);
        if (lane == 0) shBase = s;
    }
    int i = blockIdx.x * SCANB + t;
    int v = (i < n) ? deg[i] : 0;
    int incl = v;
    #pragma unroll
    for (int o = 1; o < 32; o <<= 1) {
        int x = __shfl_up_sync(0xffffffffu, incl, o);
        if (lane >= o) incl += x;
    }
    if (lane == 31) wsum[wid] = incl;
    __syncthreads();
    if (wid == 0 && lane < 8) {
        int w = wsum[lane];
        int wi = w;
        #pragma unroll
        for (int o = 1; o < 8; o <<= 1) {
            int x = __shfl_up_sync(0xffu, wi, o);
            if (lane >= o) wi += x;
        }
        wsum[lane] = wi - w;
    }
    __syncthreads();
    int excl = incl - v + wsum[wid] + shBase;
    if (i < n) {
        off[i] = excl;
        cur[i] = excl;
        if (i == n - 1) off[n] = excl + v;
    }
}

__global__ void fillK(const int* __restrict__ ei, int* __restrict__ cur,
                      int* __restrict__ csrc, int E) {
    int i = blockIdx.x * blockDim.x + threadIdx.x;
    int stride = gridDim.x * blockDim.x;
    for (; i < E; i += stride) {
        int pos = atomicAdd(&cur[ei[E + i]], 1);
        csrc[pos] = ei[i];
    }
}

__global__ void __launch_bounds__(256)
sortZK(const int* __restrict__ off, int* __restrict__ csrc, int n,
       int* __restrict__ deg) {
    for (int i = blockIdx.x * blockDim.x + threadIdx.x; i < n;
         i += gridDim.x * blockDim.x) deg[i] = 0;

    int w = (blockIdx.x * blockDim.x + threadIdx.x) >> 5;
    int lane = threadIdx.x & 31;
    if (w >= n) return;
    int beg = off[w];
    int cnt = off[w + 1] - beg;
    if (cnt <= 1) return;
    if (cnt <= 32) {
        int v0 = (lane < cnt) ? csrc[beg + lane] : INT_MAX;
        #pragma unroll
        for (int size = 2; size <= 32; size <<= 1) {
            #pragma unroll
            for (int stride = size >> 1; stride > 0; stride >>= 1) {
                int p0 = __shfl_xor_sync(0xffffffffu, v0, stride);
                bool up0 = (size == 32) ? true : ((lane & size) == 0);
                bool lower = ((lane & stride) == 0);
                v0 = (lower == up0) ? min(v0, p0) : max(v0, p0);
            }
        }
        if (lane < cnt) csrc[beg + lane] = v0;
    } else if (cnt <= 64) {
        int v0 = (lane < cnt) ? csrc[beg + lane] : INT_MAX;
        int v1 = (32 + lane < cnt) ? csrc[beg + 32 + lane] : INT_MAX;
        #pragma unroll
        for (int size = 2; size <= 64; size <<= 1) {
            #pragma unroll
            for (int stride = size >> 1; stride > 0; stride >>= 1) {
                if (stride == 32) {
                    int lo = min(v0, v1), hi = max(v0, v1);
                    v0 = lo; v1 = hi;
                } else {
                    int p0 = __shfl_xor_sync(0xffffffffu, v0, stride);
                    int p1 = __shfl_xor_sync(0xffffffffu, v1, stride);
                    bool up0, up1;
                    if (size == 64)      { up0 = true; up1 = true; }
                    else if (size == 32) { up0 = true; up1 = false; }
                    else { up0 = ((lane & size) == 0); up1 = up0; }
                    bool lower = ((lane & stride) == 0);
                    v0 = (lower == up0) ? min(v0, p0) : max(v0, p0);
                    v1 = (lower == up1) ? min(v1, p1) : max(v1, p1);
                }
            }
        }
        if (lane < cnt) csrc[beg + lane] = v0;
        if (32 + lane < cnt) csrc[beg + 32 + lane] = v1;
    } else if (lane == 0) {
        int end = beg + cnt;
        for (int i = beg + 1; i < end; i++) {
            int key = csrc[i];
            int j = i - 1;
            while (j >= beg && csrc[j] > key) { csrc[j + 1] = csrc[j]; j--; }
            csrc[j + 1] = key;
        }
    }
}

// ---------------- folded attention vectors ----------------
__global__ void uvK(const float* __restrict__ WsrcFN, const float* __restrict__ WdstFN,
                    const float* __restrict__ aSrcFN, const float* __restrict__ aDstFN,
                    const float* __restrict__ WsrcNF, const float* __restrict__ WdstNF,
                    const float* __restrict__ aSrcNF, const float* __restrict__ aDstNF,
                    float* __restrict__ uv) {
    int t = blockIdx.x * blockDim.x + threadIdx.x;
    if (t >= 4096) return;
    int h = t & 3;
    int k = (t >> 2) & 127;
    int sv = (t >> 9) & 1;
    int rel = (t >> 10) & 1;
    int l = (t >> 11) & 1;
    const float* W;
    const float* att;
    if (rel == 0) { W = sv ? WdstFN : WsrcFN; att = sv ? aDstFN : aSrcFN; }
    else          { W = sv ? WdstNF : WsrcNF; att = sv ? aDstNF : aSrcNF; }
    W += l * DIM * DIM;
    att += l * NH * 32;
    float sum = 0.f;
    #pragma unroll 8
    for (int c = 0; c < 32; c++)
        sum += W[k * DIM + h * 32 + c] * att[h * 32 + c];
    uv[t] = sum;
}

// ---------------- fp16 weight conversion ----------------
__global__ void convWK(const float* __restrict__ WsrcFN, const float* __restrict__ WsrcNF,
                       __half* __restrict__ Wh) {
    int i = blockIdx.x * blockDim.x + threadIdx.x;
    if (i >= 4 * DIM * DIM) return;
    int rel = i >> 15;
    int rest = i & 32767;
    const float* W = rel ? WsrcNF : WsrcFN;
    Wh[i] = __float2half(W[rest]);
}

// ---------------- alpha projections ----------------
__global__ void alphaK(const float4* __restrict__ x, const float* __restrict__ vmat,
                       const float* __restrict__ umat, float4* __restrict__ asOut,
                       float4* __restrict__ adOut, int n) {
    __shared__ float sv[512];
    __shared__ float su[512];
    int t = threadIdx.x;
    for (int i = t; i < 512; i += blockDim.x) { sv[i] = vmat[i]; su[i] = umat[i]; }
    __syncthreads();
    int warp = (blockIdx.x * blockDim.x + t) >> 5;
    int lane = t & 31;
    if (warp >= n) return;
    float4 xv = x[warp * 32 + lane];
    float xj[4] = {xv.x, xv.y, xv.z, xv.w};
    float pa[4] = {0, 0, 0, 0}, pd[4] = {0, 0, 0, 0};
    int j0 = lane * 4;
    #pragma unroll
    for (int j = 0; j < 4; j++) {
        #pragma unroll
        for (int h = 0; h < 4; h++) {
            pa[h] += xj[j] * sv[(j0 + j) * 4 + h];
            pd[h] += xj[j] * su[(j0 + j) * 4 + h];
        }
    }
    #pragma unroll
    for (int o = 16; o > 0; o >>= 1) {
        #pragma unroll
        for (int h = 0; h < 4; h++) {
            pa[h] += __shfl_down_sync(0xffffffffu, pa[h], o);
            pd[h] += __shfl_down_sync(0xffffffffu, pd[h], o);
        }
    }
    if (lane == 0) {
        asOut[warp] = make_float4(pa[0], pa[1], pa[2], pa[3]);
        adOut[warp] = make_float4(pd[0], pd[1], pd[2], pd[3]);
    }
}

// ---------------- tensor-core GEMM with grid-stride tile loop ----------------
__global__ void __launch_bounds__(256)
gemmTC(const float* __restrict__ A, const __half* __restrict__ Wh,
       __half* __restrict__ C, int M, int numTiles) {
    __shared__ __half bsm[128 * 136];
    __shared__ union {
        __half a[64 * 136];
        float c[64 * 132];
    } sm;
    int t = threadIdx.x;

    {
        int r = t >> 1;
        int c0 = (t & 1) * 64;
        const uint4* src = (const uint4*)(Wh + r * DIM + c0);
        uint4* dst = (uint4*)(&bsm[r * 136 + c0]);
        #pragma unroll
        for (int i = 0; i < 8; i++) dst[i] = src[i];
    }

    int warpId = t >> 5;
    int wr = warpId & 3;
    int wc = warpId >> 2;

    for (int tile = blockIdx.x; tile < numTiles; tile += gridDim.x) {
        int rowBase = tile * 64;
        __syncthreads();

        {
            int r = t >> 2;
            int c0 = (t & 3) * 32;
            int gr = rowBase + r;
            const float4* src = (const float4*)(A + (size_t)gr * DIM + c0);
            __half* dst = &sm.a[r * 136 + c0];
            if (gr < M) {
                #pragma unroll
                for (int i = 0; i < 8; i++) {
                    float4 v = src[i];
                    *(__half2*)(dst + i * 4)     = __floats2half2_rn(v.x, v.y);
                    *(__half2*)(dst + i * 4 + 2) = __floats2half2_rn(v.z, v.w);
                }
            } else {
                #pragma unroll
                for (int i = 0; i < 8; i++) {
                    *(__half2*)(dst + i * 4)     = __half2half2(__float2half(0.f));
                    *(__half2*)(dst + i * 4 + 2) = __half2half2(__float2half(0.f));
                }
            }
        }
        __syncthreads();

        wmma::fragment<wmma::accumulator, 16, 16, 16, float> cf[4];
        #pragma unroll
        for (int j = 0; j < 4; j++) wmma::fill_fragment(cf[j], 0.f);

        #pragma unroll
        for (int k0 = 0; k0 < 8; k0++) {
            wmma::fragment<wmma::matrix_a, 16, 16, 16, __half, wmma::row_major> af;
            wmma::load_matrix_sync(af, &sm.a[(wr * 16) * 136 + k0 * 16], 136);
            #pragma unroll
            for (int j = 0; j < 4; j++) {
                wmma::fragment<wmma::matrix_b, 16, 16, 16, __half, wmma::row_major> bf;
                wmma::load_matrix_sync(bf, &bsm[(k0 * 16) * 136 + wc * 64 + j * 16], 136);
                wmma::mma_sync(cf[j], af, bf, cf[j]);
            }
        }
        __syncthreads();

        #pragma unroll
        for (int j = 0; j < 4; j++)
            wmma::store_matrix_sync(&sm.c[(wr * 16) * 132 + wc * 64 + j * 16], cf[j], 132,
                                    wmma::mem_row_major);
        __syncthreads();

        {
            int r = t >> 2;
            int c0 = (t & 3) * 32;
            int gr = rowBase + r;
            if (gr < M) {
                const float* src = &sm.c[r * 132 + c0];
                __half2* dst = (__half2*)(C + (size_t)gr * DIM + c0);
                #pragma unroll
                for (int i = 0; i < 16; i++)
                    dst[i] = __floats2half2_rn(src[2 * i], src[2 * i + 1]);
            }
        }
    }
}

// ---------------- fused softmax-stats + aggregation + bias + ELU (R7 version) ----------------
__global__ void __launch_bounds__(256)
fusedAggK(const int* __restrict__ off, const int* __restrict__ csrc,
          const float4* __restrict__ as4, const float* __restrict__ as1,
          const float4* __restrict__ ad,
          const __half* __restrict__ hs, const float* __restrict__ bias,
          float4* __restrict__ out, int n) {
    __shared__ float see[8][MAXDEG][4];
    __shared__ int ssrc[8][MAXDEG];
    int w = threadIdx.x >> 5;
    int lane = threadIdx.x & 31;
    int d = blockIdx.x * 8 + w;
    if (d >= n) return;

    int beg = off[d], end = off[d + 1];
    int deg = end - beg;
    bool cached = (deg <= MAXDEG);

    float4 adv = ad[d];
    float adh4[4] = {adv.x, adv.y, adv.z, adv.w};
    float m[4] = {-1e30f, -1e30f, -1e30f, -1e30f};
    float s[4] = {0.f, 0.f, 0.f, 0.f};

    for (int i = lane; i < deg; i += 32) {
        int src = csrc[beg + i];
        float4 av = as4[src];
        float ev[4] = {av.x + adh4[0], av.y + adh4[1], av.z + adh4[2], av.w + adh4[3]};
        float ee[4];
        #pragma unroll
        for (int h = 0; h < 4; h++) {
            float e = ev[h] > 0.f ? ev[h] : 0.2f * ev[h];
            ee[h] = e;
            if (e > m[h]) {
                s[h] = s[h] * __expf(m[h] - e) + 1.f;
                m[h] = e;
            } else {
                s[h] += __expf(e - m[h]);
            }
        }
        if (cached) {
            ssrc[w][i] = src;
            *(float4*)(&see[w][i][0]) = make_float4(ee[0], ee[1], ee[2], ee[3]);
        }
    }
    #pragma unroll
    for (int o = 16; o > 0; o >>= 1) {
        #pragma unroll
        for (int h = 0; h < 4; h++) {
            float om = __shfl_xor_sync(0xffffffffu, m[h], o);
            float os = __shfl_xor_sync(0xffffffffu, s[h], o);
            float nm = fmaxf(m[h], om);
            s[h] = s[h] * __expf(m[h] - nm) + os * __expf(om - nm);
            m[h] = nm;
        }
    }
    float rAll[4];
    #pragma unroll
    for (int h = 0; h < 4; h++) rAll[h] = 1.f / (s[h] + 1e-16f);

    if (cached) {
        for (int i = lane; i < deg; i += 32) {
            float4 e4 = *(float4*)(&see[w][i][0]);
            e4.x = __expf(e4.x - m[0]) * rAll[0];
            e4.y = __expf(e4.y - m[1]) * rAll[1];
            e4.z = __expf(e4.z - m[2]) * rAll[2];
            e4.w = __expf(e4.w - m[3]) * rAll[3];
            *(float4*)(&see[w][i][0]) = e4;
        }
    }
    __syncwarp();

    int h = lane >> 3;
    float mh = m[h];
    float rh = rAll[h];
    float adh = adh4[h];

    float4 acc = make_float4(0.f, 0.f, 0.f, 0.f);
    for (int e = 0; e < deg; e++) {
        int src;
        float wgt;
        if (cached) {
            src = ssrc[w][e];
            wgt = see[w][e][h];
        } else {
            src = csrc[beg + e];
            float a = __ldg(&as1[src * 4 + h]);
            float ev = a + adh;
            float ee = ev > 0.f ? ev : 0.2f * ev;
            wgt = __expf(ee - mh) * rh;
        }
        const __half2* hp = reinterpret_cast<const __half2*>(hs + src * DIM) + lane * 2;
        __half2 p0 = hp[0], p1 = hp[1];
        float2 f0 = __half22float2(p0);
        float2 f1 = __half22float2(p1);
        acc.x += wgt * f0.x;
        acc.y += wgt * f0.y;
        acc.z += wgt * f1.x;
        acc.w += wgt * f1.y;
    }
    float4 b = *(const float4*)(bias + lane * 4);
    acc.x += b.x; acc.y += b.y; acc.z += b.z; acc.w += b.w;
    acc.x = acc.x > 0.f ? acc.x : expm1f(acc.x);
    acc.y = acc.y > 0.f ? acc.y : expm1f(acc.y);
    acc.z = acc.z > 0.f ? acc.z : expm1f(acc.z);
    acc.w = acc.w > 0.f ? acc.w : expm1f(acc.w);
    out[d * 32 + lane] = acc;
}

// ---------------- driver ----------------
extern "C" void kernel_launch(void* const* d_in, const int* in_sizes, int n_in,
                              void* d_out, int out_size) {
    const float* x_food  = (const float*)d_in[0];
    const float* x_nut   = (const float*)d_in[1];
    const float* WsrcFN  = (const float*)d_in[2];
    const float* WdstFN  = (const float*)d_in[3];
    const float* aSrcFN  = (const float*)d_in[4];
    const float* aDstFN  = (const float*)d_in[5];
    const float* biasFN  = (const float*)d_in[6];
    const float* WsrcNF  = (const float*)d_in[7];
    const float* WdstNF  = (const float*)d_in[8];
    const float* aSrcNF  = (const float*)d_in[9];
    const float* aDstNF  = (const float*)d_in[10];
    const float* biasNF  = (const float*)d_in[11];
    const int*   ei_fn   = (const int*)d_in[12];
    const int*   ei_nf   = (const int*)d_in[13];
    float* out = (float*)d_out;

    int NF = in_sizes[0] / DIM;
    int NN = in_sizes[1] / DIM;
    int E  = in_sizes[12] / 2;

    __half *hsA, *hsB, *Wh;
    float *hfood, *hnut, *asA, *adA, *asB, *adB, *as2A, *ad2A, *as2B, *ad2B, *uv;
    int *deg, *cur, *bsum, *offA, *offB, *srcA, *srcB;
    cudaGetSymbolAddress((void**)&hsA, g_hsA);
    cudaGetSymbolAddress((void**)&hsB, g_hsB);
    cudaGetSymbolAddress((void**)&Wh, g_Wh);
    cudaGetSymbolAddress((void**)&hfood, g_hfood);
    cudaGetSymbolAddress((void**)&hnut, g_hnut);
    cudaGetSymbolAddress((void**)&asA, g_asA);
    cudaGetSymbolAddress((void**)&adA, g_adA);
    cudaGetSymbolAddress((void**)&asB, g_asB);
    cudaGetSymbolAddress((void**)&adB, g_adB);
    cudaGetSymbolAddress((void**)&as2A, g_as2A);
    cudaGetSymbolAddress((void**)&ad2A, g_ad2A);
    cudaGetSymbolAddress((void**)&as2B, g_as2B);
    cudaGetSymbolAddress((void**)&ad2B, g_ad2B);
    cudaGetSymbolAddress((void**)&uv, g_uv);
    cudaGetSymbolAddress((void**)&deg, g_deg);
    cudaGetSymbolAddress((void**)&cur, g_cur);
    cudaGetSymbolAddress((void**)&bsum, g_bsum);
    cudaGetSymbolAddress((void**)&offA, g_offA);
    cudaGetSymbolAddress((void**)&offB, g_offB);
    cudaGetSymbolAddress((void**)&srcA, g_srcA);
    cudaGetSymbolAddress((void**)&srcB, g_srcB);

    int* degA = deg;
    int* degB = deg + MAXN;
    int* curA = cur;
    int* curB = cur + MAXN;
    int* bsumA = bsum;
    int* bsumB = bsum + 256;

    int warpBlk_NN = (NN + 7) / 8;
    int warpBlk_NF = (NF + 7) / 8;
    int gemmTiles_NF = (NF + 63) / 64;
    int gemmTiles_NN = (NN + 63) / 64;
    const int GEMM_GRID = 304;
    int scanBlkA = (NN + SCANB - 1) / SCANB;
    int scanBlkB = (NF + SCANB - 1) / SCANB;

    static cudaStream_t s1 = nullptr, s2 = nullptr, s3 = nullptr;
    static cudaEvent_t eR, eCW, eAl0, eCA, eG0B, eA0, eA0p, eB0, eB0p, eB1;
    if (!s1) {
        cudaStreamCreateWithFlags(&s1, cudaStreamNonBlocking);
        cudaStreamCreateWithFlags(&s2, cudaStreamNonBlocking);
        cudaStreamCreateWithFlags(&s3, cudaStreamNonBlocking);
        cudaEventCreateWithFlags(&eR,   cudaEventDisableTiming);
        cudaEventCreateWithFlags(&eCW,  cudaEventDisableTiming);
        cudaEventCreateWithFlags(&eAl0, cudaEventDisableTiming);
        cudaEventCreateWithFlags(&eCA,  cudaEventDisableTiming);
        cudaEventCreateWithFlags(&eG0B, cudaEventDisableTiming);
        cudaEventCreateWithFlags(&eA0,  cudaEventDisableTiming);
        cudaEventCreateWithFlags(&eA0p, cudaEventDisableTiming);
        cudaEventCreateWithFlags(&eB0,  cudaEventDisableTiming);
        cudaEventCreateWithFlags(&eB0p, cudaEventDisableTiming);
        cudaEventCreateWithFlags(&eB1,  cudaEventDisableTiming);
    }

    const float* v_fn0 = uv + 0 * 2048 + 0 * 1024 + 0 * 512;
    const float* u_fn0 = uv + 0 * 2048 + 0 * 1024 + 1 * 512;
    const float* v_nf0 = uv + 0 * 2048 + 1 * 1024 + 0 * 512;
    const float* u_nf0 = uv + 0 * 2048 + 1 * 1024 + 1 * 512;
    const float* v_fn1 = uv + 1 * 2048 + 0 * 1024 + 0 * 512;
    const float* u_fn1 = uv + 1 * 2048 + 0 * 1024 + 1 * 512;
    const float* v_nf1 = uv + 1 * 2048 + 1 * 1024 + 0 * 512;
    const float* u_nf1 = uv + 1 * 2048 + 1 * 1024 + 1 * 512;
    const __half* Wh_fn0 = Wh + 0 * DIM * DIM;
    const __half* Wh_fn1 = Wh + 1 * DIM * DIM;
    const __half* Wh_nf0 = Wh + 2 * DIM * DIM;
    const __half* Wh_nf1 = Wh + 3 * DIM * DIM;
    float* out_food = out;
    float* out_nut  = out + (size_t)NF * DIM;

    // ---- fork ----
    cudaEventRecord(eR, 0);
    cudaStreamWaitEvent(s1, eR, 0);
    cudaStreamWaitEvent(s2, eR, 0);
    cudaStreamWaitEvent(s3, eR, 0);

    // S0: weights + layer-0 alphas FIRST (eAl0 fires early), then gemm0A
    convWK<<<(4 * DIM * DIM + 255) / 256, 256>>>(WsrcFN, WsrcNF, Wh);
    cudaEventRecord(eCW, 0);
    uvK<<<16, 256>>>(WsrcFN, WdstFN, aSrcFN, aDstFN, WsrcNF, WdstNF, aSrcNF, aDstNF, uv);
    alphaK<<<warpBlk_NF, 256>>>((const float4*)x_food, v_fn0, u_nf0,
                                (float4*)asA, (float4*)adB, NF);
    alphaK<<<warpBlk_NN, 256>>>((const float4*)x_nut, v_nf0, u_fn0,
                                (float4*)asB, (float4*)adA, NN);
    cudaEventRecord(eAl0, 0);
    gemmTC<<<GEMM_GRID, 256>>>(x_food, Wh_fn0, hsA, NF, gemmTiles_NF);

    // S1: CSR-A
    histK<<<1024, 256, 0, s1>>>(ei_fn + E, degA, E);
    scanSumK<<<scanBlkA, SCANB, 0, s1>>>(degA, bsumA, NN);
    scanApplyK<<<scanBlkA, SCANB, 0, s1>>>(degA, bsumA, offA, curA, NN);
    fillK<<<1024, 256, 0, s1>>>(ei_fn, curA, srcA, E);
    sortZK<<<(NN + 7) / 8, 256, 0, s1>>>(offA, srcA, NN, degA);
    cudaEventRecord(eCA, s1);

    // S3: gemm0B in parallel with CSR-B
    cudaStreamWaitEvent(s3, eCW, 0);
    gemmTC<<<GEMM_GRID, 256, 0, s3>>>(x_nut, Wh_nf0, hsB, NN, gemmTiles_NN);
    cudaEventRecord(eG0B, s3);

    // S2: CSR-B
    histK<<<1024, 256, 0, s2>>>(ei_nf + E, degB, E);
    scanSumK<<<scanBlkB, SCANB, 0, s2>>>(degB, bsumB, NF);
    scanApplyK<<<scanBlkB, SCANB, 0, s2>>>(degB, bsumB, offB, curB, NF);
    fillK<<<1024, 256, 0, s2>>>(ei_nf, curB, srcB, E);
    sortZK<<<(NF + 7) / 8, 256, 0, s2>>>(offB, srcB, NF, degB);

    // S2: layer-0 nf agg (-> hfood), then layer-1 food alphas
    cudaStreamWaitEvent(s2, eAl0, 0);
    cudaStreamWaitEvent(s2, eG0B, 0);
    fusedAggK<<<warpBlk_NF, 256, 0, s2>>>(offB, srcB, (const float4*)asB, asB,
                                          (const float4*)adB, hsB, biasNF,
                                          (float4*)hfood, NF);
    cudaEventRecord(eB0, s2);   // hfood ready
    alphaK<<<warpBlk_NF, 256, 0, s2>>>((const float4*)hfood, v_fn1, u_nf1,
                                       (float4*)as2A, (float4*)ad2B, NF);
    cudaEventRecord(eB0p, s2);  // food alphas ready

    // S0: layer-0 fn agg (-> hnut), then layer-1 nut alphas
    cudaStreamWaitEvent(0, eCA, 0);
    fusedAggK<<<warpBlk_NN, 256>>>(offA, srcA, (const float4*)asA, asA,
                                   (const float4*)adA, hsA, biasFN,
                                   (float4*)hnut, NN);
    cudaEventRecord(eA0, 0);    // hnut ready
    alphaK<<<warpBlk_NN, 256>>>((const float4*)hnut, v_nf1, u_fn1,
                                (float4*)as2B, (float4*)ad2A, NN);
    cudaEventRecord(eA0p, 0);   // nut alphas ready

    // S0: layer-1 fn chain (gemm hidden-overlaps S2's alpha)
    cudaStreamWaitEvent(0, eB0, 0);
    gemmTC<<<GEMM_GRID, 256>>>(hfood, Wh_fn1, hsA, NF, gemmTiles_NF);
    cudaStreamWaitEvent(0, eB0p, 0);
    fusedAggK<<<warpBlk_NN, 256>>>(offA, srcA, (const float4*)as2A, as2A,
                                   (const float4*)ad2A, hsA, biasFN + DIM,
                                   (float4*)out_nut, NN);

    // S2: layer-1 nf chain
    cudaStreamWaitEvent(s2, eA0, 0);
    gemmTC<<<GEMM_GRID, 256, 0, s2>>>(hnut, Wh_nf1, hsB, NN, gemmTiles_NN);
    cudaStreamWaitEvent(s2, eA0p, 0);
    fusedAggK<<<warpBlk_NF, 256, 0, s2>>>(offB, srcB, (const float4*)as2B, as2B,
                                          (const float4*)ad2B, hsB, biasNF + DIM,
                                          (float4*)out_food, NF);
    cudaEventRecord(eB1, s2);

    // ---- join ----
    cudaStreamWaitEvent(0, eB1, 0);
}

// round 13
// speedup vs baseline: 1.3335x; 1.2160x over previous
#include <cuda_runtime.h>
#include <cuda_fp16.h>
#include <mma.h>
#include <math.h>
#include <limits.h>

using namespace nvcuda;

#define DIM 128
#define NH 4
#define MAXN 50048
#define MAXE 800032
#define MAXDEG 96
#define SCANB 256
#define BCOLS 144      // 128 W cols + 4 v + 4 u + 8 pad
#define BSTRIDE 152    // smem ldm (halves)
#define CSTRIDE 148    // smem ldm (floats)

// ---------------- scratch (static device globals; no allocation) ----------------
__device__ __half g_hsA[MAXN * DIM];
__device__ __half g_hsB[MAXN * DIM];
__device__ __half g_Whx[4 * DIM * BCOLS];  // [side*2+l][128][144]
__device__ float g_hfood[MAXN * DIM];
__device__ float g_hnut[MAXN * DIM];
__device__ float g_asA[MAXN * NH];
__device__ float g_adA[MAXN * NH];
__device__ float g_asB[MAXN * NH];
__device__ float g_adB[MAXN * NH];
__device__ float g_as2A[MAXN * NH];
__device__ float g_ad2A[MAXN * NH];
__device__ float g_as2B[MAXN * NH];
__device__ float g_ad2B[MAXN * NH];
__device__ float g_uv[4096];
__device__ int   g_deg[2 * MAXN];     // zero-init; re-zeroed by sortZK epilogue
__device__ int   g_cur[2 * MAXN];
__device__ int   g_bsum[2 * 256];
__device__ int   g_offA[MAXN + 1];
__device__ int   g_offB[MAXN + 1];
__device__ int   g_srcA[MAXE];
__device__ int   g_srcB[MAXE];

// ---------------- CSR build ----------------
__global__ void histK(const int* __restrict__ dst, int* __restrict__ deg, int E) {
    int i = blockIdx.x * blockDim.x + threadIdx.x;
    int stride = gridDim.x * blockDim.x;
    for (; i < E; i += stride) atomicAdd(&deg[dst[i]], 1);
}

__global__ void scanSumK(const int* __restrict__ deg, int* __restrict__ bsum, int n) {
    __shared__ int wsum[8];
    int t = threadIdx.x;
    int i = blockIdx.x * SCANB + t;
    int v = (i < n) ? deg[i] : 0;
    #pragma unroll
    for (int o = 16; o > 0; o >>= 1) v += __shfl_down_sync(0xffffffffu, v, o);
    if ((t & 31) == 0) wsum[t >> 5] = v;
    __syncthreads();
    if (t == 0) {
        int s = 0;
        #pragma unroll
        for (int w = 0; w < 8; w++) s += wsum[w];
        bsum[blockIdx.x] = s;
    }
}

__global__ void scanApplyK(const int* __restrict__ deg, const int* __restrict__ bsum,
                           int* __restrict__ off, int* __restrict__ cur, int n) {
    __shared__ int wsum[8];
    __shared__ int shBase;
    int t = threadIdx.x;
    int lane = t & 31, wid = t >> 5;
    if (wid == 0) {
        int s = 0;
        for (int j = lane; j < blockIdx.x; j += 32) s += bsum[j];
        #pragma unroll
        for (int o = 16; o > 0; o >>= 1) s += __shfl_down_sync(0xffffffffu, s, o);
        if (lane == 0) shBase = s;
    }
    int i = blockIdx.x * SCANB + t;
    int v = (i < n) ? deg[i] : 0;
    int incl = v;
    #pragma unroll
    for (int o = 1; o < 32; o <<= 1) {
        int x = __shfl_up_sync(0xffffffffu, incl, o);
        if (lane >= o) incl += x;
    }
    if (lane == 31) wsum[wid] = incl;
    __syncthreads();
    if (wid == 0 && lane < 8) {
        int w = wsum[lane];
        int wi = w;
        #pragma unroll
        for (int o = 1; o < 8; o <<= 1) {
            int x = __shfl_up_sync(0xffu, wi, o);
            if (lane >= o) wi += x;
        }
        wsum[lane] = wi - w;
    }
    __syncthreads();
    int excl = incl - v + wsum[wid] + shBase;
    if (i < n) {
        off[i] = excl;
        cur[i] = excl;
        if (i == n - 1) off[n] = excl + v;
    }
}

__global__ void fillK(const int* __restrict__ ei, int* __restrict__ cur,
                      int* __restrict__ csrc, int E) {
    int i = blockIdx.x * blockDim.x + threadIdx.x;
    int stride = gridDim.x * blockDim.x;
    for (; i < E; i += stride) {
        int pos = atomicAdd(&cur[ei[E + i]], 1);
        csrc[pos] = ei[i];
    }
}

__global__ void __launch_bounds__(256)
sortZK(const int* __restrict__ off, int* __restrict__ csrc, int n,
       int* __restrict__ deg) {
    for (int i = blockIdx.x * blockDim.x + threadIdx.x; i < n;
         i += gridDim.x * blockDim.x) deg[i] = 0;

    int w = (blockIdx.x * blockDim.x + threadIdx.x) >> 5;
    int lane = threadIdx.x & 31;
    if (w >= n) return;
    int beg = off[w];
    int cnt = off[w + 1] - beg;
    if (cnt <= 1) return;
    if (cnt <= 32) {
        int v0 = (lane < cnt) ? csrc[beg + lane] : INT_MAX;
        #pragma unroll
        for (int size = 2; size <= 32; size <<= 1) {
            #pragma unroll
            for (int stride = size >> 1; stride > 0; stride >>= 1) {
                int p0 = __shfl_xor_sync(0xffffffffu, v0, stride);
                bool up0 = (size == 32) ? true : ((lane & size) == 0);
                bool lower = ((lane & stride) == 0);
                v0 = (lower == up0) ? min(v0, p0) : max(v0, p0);
            }
        }
        if (lane < cnt) csrc[beg + lane] = v0;
    } else if (cnt <= 64) {
        int v0 = (lane < cnt) ? csrc[beg + lane] : INT_MAX;
        int v1 = (32 + lane < cnt) ? csrc[beg + 32 + lane] : INT_MAX;
        #pragma unroll
        for (int size = 2; size <= 64; size <<= 1) {
            #pragma unroll
            for (int stride = size >> 1; stride > 0; stride >>= 1) {
                if (stride == 32) {
                    int lo = min(v0, v1), hi = max(v0, v1);
                    v0 = lo; v1 = hi;
                } else {
                    int p0 = __shfl_xor_sync(0xffffffffu, v0, stride);
                    int p1 = __shfl_xor_sync(0xffffffffu, v1, stride);
                    bool up0, up1;
                    if (size == 64)      { up0 = true; up1 = true; }
                    else if (size == 32) { up0 = true; up1 = false; }
                    else { up0 = ((lane & size) == 0); up1 = up0; }
                    bool lower = ((lane & stride) == 0);
                    v0 = (lower == up0) ? min(v0, p0) : max(v0, p0);
                    v1 = (lower == up1) ? min(v1, p1) : max(v1, p1);
                }
            }
        }
        if (lane < cnt) csrc[beg + lane] = v0;
        if (32 + lane < cnt) csrc[beg + 32 + lane] = v1;
    } else if (lane == 0) {
        int end = beg + cnt;
        for (int i = beg + 1; i < end; i++) {
            int key = csrc[i];
            int j = i - 1;
            while (j >= beg && csrc[j] > key) { csrc[j + 1] = csrc[j]; j--; }
            csrc[j + 1] = key;
        }
    }
}

// ---------------- folded attention vectors ----------------
__global__ void uvK(const float* __restrict__ WsrcFN, const float* __restrict__ WdstFN,
                    const float* __restrict__ aSrcFN, const float* __restrict__ aDstFN,
                    const float* __restrict__ WsrcNF, const float* __restrict__ WdstNF,
                    const float* __restrict__ aSrcNF, const float* __restrict__ aDstNF,
                    float* __restrict__ uv) {
    int t = blockIdx.x * blockDim.x + threadIdx.x;
    if (t >= 4096) return;
    int h = t & 3;
    int k = (t >> 2) & 127;
    int sv = (t >> 9) & 1;
    int rel = (t >> 10) & 1;
    int l = (t >> 11) & 1;
    const float* W;
    const float* att;
    if (rel == 0) { W = sv ? WdstFN : WsrcFN; att = sv ? aDstFN : aSrcFN; }
    else          { W = sv ? WdstNF : WsrcNF; att = sv ? aDstNF : aSrcNF; }
    W += l * DIM * DIM;
    att += l * NH * 32;
    float sum = 0.f;
    #pragma unroll 8
    for (int c = 0; c < 32; c++)
        sum += W[k * DIM + h * 32 + c] * att[h * 32 + c];
    uv[t] = sum;
}

// ---------------- extended fp16 weight pack: [Wsrc | v | u | 0] ----------------
__global__ void convWxK(const float* __restrict__ WsrcFN, const float* __restrict__ WsrcNF,
                        const float* __restrict__ uv, __half* __restrict__ Whx) {
    int i = blockIdx.x * blockDim.x + threadIdx.x;
    if (i >= 4 * DIM * BCOLS) return;
    int mat = i / (DIM * BCOLS);     // side*2 + l
    int rem = i % (DIM * BCOLS);
    int k = rem / BCOLS;
    int c = rem % BCOLS;
    int side = mat >> 1, l = mat & 1;
    float val;
    if (c < 128) {
        const float* W = side ? WsrcNF : WsrcFN;
        val = W[l * DIM * DIM + k * DIM + c];
    } else if (c < 136) {
        int h = (c - 128) & 3;
        int svsel = (c - 128) >> 2;          // 0 = v (src), 1 = u (dst of other rel)
        int rel = svsel ? (1 - side) : side; // food: v_fn,u_nf ; nut: v_nf,u_fn
        val = uv[l * 2048 + rel * 1024 + svsel * 512 + k * 4 + h];
    } else {
        val = 0.f;
    }
    Whx[i] = __float2half(val);
}

// ---------------- tensor-core GEMM + fused alpha projections ----------------
// C[M,128] = A@W (fp16 out); asOut/adOut[M,4] = A@v, A@u (fp32 out, cols 128..135).
__global__ void __launch_bounds__(256)
gemmTC(const float* __restrict__ A, const __half* __restrict__ Whx,
       __half* __restrict__ C, float4* __restrict__ asOut, float4* __restrict__ adOut,
       int M, int numTiles) {
    __shared__ __half bsm[128 * BSTRIDE];
    __shared__ union {
        __half a[64 * 136];
        float c[64 * CSTRIDE];
    } sm;
    int t = threadIdx.x;

    // stage Whx (128 x 144 fp16): 18 uint4/row, 2 threads/row x 9
    {
        int r = t >> 1;
        int hv = t & 1;
        const uint4* src = (const uint4*)(Whx + r * BCOLS) + hv * 9;
        uint4* dst = (uint4*)(&bsm[r * BSTRIDE]) + hv * 9;
        #pragma unroll
        for (int i = 0; i < 9; i++) dst[i] = src[i];
    }

    int warpId = t >> 5;
    int wr = warpId & 3;
    int wc = warpId >> 2;          // 0: cols 0..79 (5 tiles), 1: cols 80..143 (4 tiles)

    for (int tile = blockIdx.x; tile < numTiles; tile += gridDim.x) {
        int rowBase = tile * 64;
        __syncthreads();           // bsm ready / prior writeback done

        {
            int r = t >> 2;
            int c0 = (t & 3) * 32;
            int gr = rowBase + r;
            const float4* src = (const float4*)(A + (size_t)gr * DIM + c0);
            __half* dst = &sm.a[r * 136 + c0];
            if (gr < M) {
                #pragma unroll
                for (int i = 0; i < 8; i++) {
                    float4 v = src[i];
                    *(__half2*)(dst + i * 4)     = __floats2half2_rn(v.x, v.y);
                    *(__half2*)(dst + i * 4 + 2) = __floats2half2_rn(v.z, v.w);
                }
            } else {
                #pragma unroll
                for (int i = 0; i < 8; i++) {
                    *(__half2*)(dst + i * 4)     = __half2half2(__float2half(0.f));
                    *(__half2*)(dst + i * 4 + 2) = __half2half2(__float2half(0.f));
                }
            }
        }
        __syncthreads();

        wmma::fragment<wmma::accumulator, 16, 16, 16, float> cf[5];
        #pragma unroll
        for (int j = 0; j < 5; j++) wmma::fill_fragment(cf[j], 0.f);

        if (wc == 0) {
            #pragma unroll
            for (int k0 = 0; k0 < 8; k0++) {
                wmma::fragment<wmma::matrix_a, 16, 16, 16, __half, wmma::row_major> af;
                wmma::load_matrix_sync(af, &sm.a[(wr * 16) * 136 + k0 * 16], 136);
                #pragma unroll
                for (int j = 0; j < 5; j++) {
                    wmma::fragment<wmma::matrix_b, 16, 16, 16, __half, wmma::row_major> bf;
                    wmma::load_matrix_sync(bf, &bsm[(k0 * 16) * BSTRIDE + j * 16], BSTRIDE);
                    wmma::mma_sync(cf[j], af, bf, cf[j]);
                }
            }
        } else {
            #pragma unroll
            for (int k0 = 0; k0 < 8; k0++) {
                wmma::fragment<wmma::matrix_a, 16, 16, 16, __half, wmma::row_major> af;
                wmma::load_matrix_sync(af, &sm.a[(wr * 16) * 136 + k0 * 16], 136);
                #pragma unroll
                for (int j = 0; j < 4; j++) {
                    wmma::fragment<wmma::matrix_b, 16, 16, 16, __half, wmma::row_major> bf;
                    wmma::load_matrix_sync(bf, &bsm[(k0 * 16) * BSTRIDE + 80 + j * 16], BSTRIDE);
                    wmma::mma_sync(cf[j], af, bf, cf[j]);
                }
            }
        }
        __syncthreads();           // all warps done reading sm.a before c overwrites union

        if (wc == 0) {
            #pragma unroll
            for (int j = 0; j < 5; j++)
                wmma::store_matrix_sync(&sm.c[(wr * 16) * CSTRIDE + j * 16], cf[j],
                                        CSTRIDE, wmma::mem_row_major);
        } else {
            #pragma unroll
            for (int j = 0; j < 4; j++)
                wmma::store_matrix_sync(&sm.c[(wr * 16) * CSTRIDE + 80 + j * 16], cf[j],
                                        CSTRIDE, wmma::mem_row_major);
        }
        __syncthreads();

        {
            int r = t >> 2;
            int c0 = (t & 3) * 32;
            int gr = rowBase + r;
            if (gr < M) {
                const float* src = &sm.c[r * CSTRIDE + c0];
                __half2* dst = (__half2*)(C + (size_t)gr * DIM + c0);
                #pragma unroll
                for (int i = 0; i < 16; i++)
                    dst[i] = __floats2half2_rn(src[2 * i], src[2 * i + 1]);
                if ((t & 3) == 0) {  // alpha writeback (fp32 from accumulator)
                    asOut[gr] = *(const float4*)(&sm.c[r * CSTRIDE + 128]);
                    adOut[gr] = *(const float4*)(&sm.c[r * CSTRIDE + 132]);
                }
            }
        }
    }
}

// ---------------- fused softmax-stats + aggregation + bias + ELU ----------------
__global__ void __launch_bounds__(256)
fusedAggK(const int* __restrict__ off, const int* __restrict__ csrc,
          const float4* __restrict__ as4, const float* __restrict__ as1,
          const float4* __restrict__ ad,
          const __half* __restrict__ hs, const float* __restrict__ bias,
          float4* __restrict__ out, int n) {
    __shared__ float see[8][MAXDEG][4];
    __shared__ int ssrc[8][MAXDEG];
    int w = threadIdx.x >> 5;
    int lane = threadIdx.x & 31;
    int d = blockIdx.x * 8 + w;
    if (d >= n) return;

    int beg = off[d], end = off[d + 1];
    int deg = end - beg;
    bool cached = (deg <= MAXDEG);

    float4 adv = ad[d];
    float adh4[4] = {adv.x, adv.y, adv.z, adv.w};
    float m[4] = {-1e30f, -1e30f, -1e30f, -1e30f};
    float s[4] = {0.f, 0.f, 0.f, 0.f};

    for (int i = lane; i < deg; i += 32) {
        int src = csrc[beg + i];
        float4 av = as4[src];
        float ev[4] = {av.x + adh4[0], av.y + adh4[1], av.z + adh4[2], av.w + adh4[3]};
        float ee[4];
        #pragma unroll
        for (int h = 0; h < 4; h++) {
            float e = ev[h] > 0.f ? ev[h] : 0.2f * ev[h];
            ee[h] = e;
            if (e > m[h]) {
                s[h] = s[h] * __expf(m[h] - e) + 1.f;
                m[h] = e;
            } else {
                s[h] += __expf(e - m[h]);
            }
        }
        if (cached) {
            ssrc[w][i] = src;
            *(float4*)(&see[w][i][0]) = make_float4(ee[0], ee[1], ee[2], ee[3]);
        }
    }
    #pragma unroll
    for (int o = 16; o > 0; o >>= 1) {
        #pragma unroll
        for (int h = 0; h < 4; h++) {
            float om = __shfl_xor_sync(0xffffffffu, m[h], o);
            float os = __shfl_xor_sync(0xffffffffu, s[h], o);
            float nm = fmaxf(m[h], om);
            s[h] = s[h] * __expf(m[h] - nm) + os * __expf(om - nm);
            m[h] = nm;
        }
    }
    float rAll[4];
    #pragma unroll
    for (int h = 0; h < 4; h++) rAll[h] = 1.f / (s[h] + 1e-16f);

    if (cached) {
        for (int i = lane; i < deg; i += 32) {
            float4 e4 = *(float4*)(&see[w][i][0]);
            e4.x = __expf(e4.x - m[0]) * rAll[0];
            e4.y = __expf(e4.y - m[1]) * rAll[1];
            e4.z = __expf(e4.z - m[2]) * rAll[2];
            e4.w = __expf(e4.w - m[3]) * rAll[3];
            *(float4*)(&see[w][i][0]) = e4;
        }
    }
    __syncwarp();

    int h = lane >> 3;
    float mh = m[h];
    float rh = rAll[h];
    float adh = adh4[h];

    float4 acc = make_float4(0.f, 0.f, 0.f, 0.f);
    for (int e = 0; e < deg; e++) {
        int src;
        float wgt;
        if (cached) {
            src = ssrc[w][e];
            wgt = see[w][e][h];
        } else {
            src = csrc[beg + e];
            float a = __ldg(&as1[src * 4 + h]);
            float ev = a + adh;
            float ee = ev > 0.f ? ev : 0.2f * ev;
            wgt = __expf(ee - mh) * rh;
        }
        const __half2* hp = reinterpret_cast<const __half2*>(hs + src * DIM) + lane * 2;
        __half2 p0 = hp[0], p1 = hp[1];
        float2 f0 = __half22float2(p0);
        float2 f1 = __half22float2(p1);
        acc.x += wgt * f0.x;
        acc.y += wgt * f0.y;
        acc.z += wgt * f1.x;
        acc.w += wgt * f1.y;
    }
    float4 b = *(const float4*)(bias + lane * 4);
    acc.x += b.x; acc.y += b.y; acc.z += b.z; acc.w += b.w;
    acc.x = acc.x > 0.f ? acc.x : expm1f(acc.x);
    acc.y = acc.y > 0.f ? acc.y : expm1f(acc.y);
    acc.z = acc.z > 0.f ? acc.z : expm1f(acc.z);
    acc.w = acc.w > 0.f ? acc.w : expm1f(acc.w);
    out[d * 32 + lane] = acc;
}

// ---------------- driver ----------------
extern "C" void kernel_launch(void* const* d_in, const int* in_sizes, int n_in,
                              void* d_out, int out_size) {
    const float* x_food  = (const float*)d_in[0];
    const float* x_nut   = (const float*)d_in[1];
    const float* WsrcFN  = (const float*)d_in[2];
    const float* WdstFN  = (const float*)d_in[3];
    const float* aSrcFN  = (const float*)d_in[4];
    const float* aDstFN  = (const float*)d_in[5];
    const float* biasFN  = (const float*)d_in[6];
    const float* WsrcNF  = (const float*)d_in[7];
    const float* WdstNF  = (const float*)d_in[8];
    const float* aSrcNF  = (const float*)d_in[9];
    const float* aDstNF  = (const float*)d_in[10];
    const float* biasNF  = (const float*)d_in[11];
    const int*   ei_fn   = (const int*)d_in[12];
    const int*   ei_nf   = (const int*)d_in[13];
    float* out = (float*)d_out;

    int NF = in_sizes[0] / DIM;
    int NN = in_sizes[1] / DIM;
    int E  = in_sizes[12] / 2;

    __half *hsA, *hsB, *Whx;
    float *hfood, *hnut, *asA, *adA, *asB, *adB, *as2A, *ad2A, *as2B, *ad2B, *uv;
    int *deg, *cur, *bsum, *offA, *offB, *srcA, *srcB;
    cudaGetSymbolAddress((void**)&hsA, g_hsA);
    cudaGetSymbolAddress((void**)&hsB, g_hsB);
    cudaGetSymbolAddress((void**)&Whx, g_Whx);
    cudaGetSymbolAddress((void**)&hfood, g_hfood);
    cudaGetSymbolAddress((void**)&hnut, g_hnut);
    cudaGetSymbolAddress((void**)&asA, g_asA);
    cudaGetSymbolAddress((void**)&adA, g_adA);
    cudaGetSymbolAddress((void**)&asB, g_asB);
    cudaGetSymbolAddress((void**)&adB, g_adB);
    cudaGetSymbolAddress((void**)&as2A, g_as2A);
    cudaGetSymbolAddress((void**)&ad2A, g_ad2A);
    cudaGetSymbolAddress((void**)&as2B, g_as2B);
    cudaGetSymbolAddress((void**)&ad2B, g_ad2B);
    cudaGetSymbolAddress((void**)&uv, g_uv);
    cudaGetSymbolAddress((void**)&deg, g_deg);
    cudaGetSymbolAddress((void**)&cur, g_cur);
    cudaGetSymbolAddress((void**)&bsum, g_bsum);
    cudaGetSymbolAddress((void**)&offA, g_offA);
    cudaGetSymbolAddress((void**)&offB, g_offB);
    cudaGetSymbolAddress((void**)&srcA, g_srcA);
    cudaGetSymbolAddress((void**)&srcB, g_srcB);

    int* degA = deg;
    int* degB = deg + MAXN;
    int* curA = cur;
    int* curB = cur + MAXN;
    int* bsumA = bsum;
    int* bsumB = bsum + 256;

    int warpBlk_NN = (NN + 7) / 8;
    int warpBlk_NF = (NF + 7) / 8;
    int gemmTiles_NF = (NF + 63) / 64;
    int gemmTiles_NN = (NN + 63) / 64;
    const int GEMM_GRID = 296;   // 2 blocks/SM at ~77KB smem
    int scanBlkA = (NN + SCANB - 1) / SCANB;
    int scanBlkB = (NF + SCANB - 1) / SCANB;

    static cudaStream_t s1 = nullptr, s2 = nullptr, s3 = nullptr;
    static cudaEvent_t eR, eCW, eG0A, eG0B, eCA, eB0, eA0, eG1A, eG1B, eB1;
    if (!s1) {
        cudaStreamCreateWithFlags(&s1, cudaStreamNonBlocking);
        cudaStreamCreateWithFlags(&s2, cudaStreamNonBlocking);
        cudaStreamCreateWithFlags(&s3, cudaStreamNonBlocking);
        cudaEventCreateWithFlags(&eR,   cudaEventDisableTiming);
        cudaEventCreateWithFlags(&eCW,  cudaEventDisableTiming);
        cudaEventCreateWithFlags(&eG0A, cudaEventDisableTiming);
        cudaEventCreateWithFlags(&eG0B, cudaEventDisableTiming);
        cudaEventCreateWithFlags(&eCA,  cudaEventDisableTiming);
        cudaEventCreateWithFlags(&eB0,  cudaEventDisableTiming);
        cudaEventCreateWithFlags(&eA0,  cudaEventDisableTiming);
        cudaEventCreateWithFlags(&eG1A, cudaEventDisableTiming);
        cudaEventCreateWithFlags(&eG1B, cudaEventDisableTiming);
        cudaEventCreateWithFlags(&eB1,  cudaEventDisableTiming);
    }

    const __half* Whx_f0 = Whx + 0 * DIM * BCOLS;  // food, layer 0
    const __half* Whx_f1 = Whx + 1 * DIM * BCOLS;  // food, layer 1
    const __half* Whx_n0 = Whx + 2 * DIM * BCOLS;  // nut, layer 0
    const __half* Whx_n1 = Whx + 3 * DIM * BCOLS;  // nut, layer 1
    float* out_food = out;
    float* out_nut  = out + (size_t)NF * DIM;

    // ---- fork ----
    cudaEventRecord(eR, 0);
    cudaStreamWaitEvent(s1, eR, 0);
    cudaStreamWaitEvent(s2, eR, 0);
    cudaStreamWaitEvent(s3, eR, 0);

    // S0: fold attention vectors, pack extended fp16 weights, layer-0 food GEMM
    uvK<<<16, 256>>>(WsrcFN, WdstFN, aSrcFN, aDstFN, WsrcNF, WdstNF, aSrcNF, aDstNF, uv);
    convWxK<<<(4 * DIM * BCOLS + 255) / 256, 256>>>(WsrcFN, WsrcNF, uv, Whx);
    cudaEventRecord(eCW, 0);
    gemmTC<<<GEMM_GRID, 256>>>(x_food, Whx_f0, hsA, (float4*)asA, (float4*)adB,
                               NF, gemmTiles_NF);
    cudaEventRecord(eG0A, 0);

    // S3: layer-0 nut GEMM (parallel with CSR builds)
    cudaStreamWaitEvent(s3, eCW, 0);
    gemmTC<<<GEMM_GRID, 256, 0, s3>>>(x_nut, Whx_n0, hsB, (float4*)asB, (float4*)adA,
                                      NN, gemmTiles_NN);
    cudaEventRecord(eG0B, s3);

    // S1: CSR-A
    histK<<<1024, 256, 0, s1>>>(ei_fn + E, degA, E);
    scanSumK<<<scanBlkA, SCANB, 0, s1>>>(degA, bsumA, NN);
    scanApplyK<<<scanBlkA, SCANB, 0, s1>>>(degA, bsumA, offA, curA, NN);
    fillK<<<1024, 256, 0, s1>>>(ei_fn, curA, srcA, E);
    sortZK<<<(NN + 7) / 8, 256, 0, s1>>>(offA, srcA, NN, degA);
    cudaEventRecord(eCA, s1);

    // S2: CSR-B
    histK<<<1024, 256, 0, s2>>>(ei_nf + E, degB, E);
    scanSumK<<<scanBlkB, SCANB, 0, s2>>>(degB, bsumB, NF);
    scanApplyK<<<scanBlkB, SCANB, 0, s2>>>(degB, bsumB, offB, curB, NF);
    fillK<<<1024, 256, 0, s2>>>(ei_nf, curB, srcB, E);
    sortZK<<<(NF + 7) / 8, 256, 0, s2>>>(offB, srcB, NF, degB);

    // S2: layer-0 nf agg (asB from gemm0B, adB from gemm0A, hsB) -> hfood
    cudaStreamWaitEvent(s2, eG0A, 0);
    cudaStreamWaitEvent(s2, eG0B, 0);
    fusedAggK<<<warpBlk_NF, 256, 0, s2>>>(offB, srcB, (const float4*)asB, asB,
                                          (const float4*)adB, hsB, biasNF,
                                          (float4*)hfood, NF);
    cudaEventRecord(eB0, s2);

    // S0: layer-0 fn agg (asA from gemm0A, adA from gemm0B, hsA) -> hnut
    cudaStreamWaitEvent(0, eCA, 0);
    cudaStreamWaitEvent(0, eG0B, 0);
    fusedAggK<<<warpBlk_NN, 256>>>(offA, srcA, (const float4*)asA, asA,
                                   (const float4*)adA, hsA, biasFN,
                                   (float4*)hnut, NN);
    cudaEventRecord(eA0, 0);

    // S0: layer-1 food GEMM (hfood -> hsA, as2A, ad2B)
    cudaStreamWaitEvent(0, eB0, 0);
    gemmTC<<<GEMM_GRID, 256>>>(hfood, Whx_f1, hsA, (float4*)as2A, (float4*)ad2B,
                               NF, gemmTiles_NF);
    cudaEventRecord(eG1A, 0);

    // S2: layer-1 nut GEMM (hnut -> hsB, as2B, ad2A)
    cudaStreamWaitEvent(s2, eA0, 0);
    gemmTC<<<GEMM_GRID, 256, 0, s2>>>(hnut, Whx_n1, hsB, (float4*)as2B, (float4*)ad2A,
                                      NN, gemmTiles_NN);
    cudaEventRecord(eG1B, s2);

    // S0: layer-1 fn agg (as2A from gemm1A, ad2A from gemm1B) -> out_nut
    cudaStreamWaitEvent(0, eG1B, 0);
    fusedAggK<<<warpBlk_NN, 256>>>(offA, srcA, (const float4*)as2A, as2A,
                                   (const float4*)ad2A, hsA, biasFN + DIM,
                                   (float4*)out_nut, NN);

    // S2: layer-1 nf agg (as2B from gemm1B, ad2B from gemm1A) -> out_food
    cudaStreamWaitEvent(s2, eG1A, 0);
    fusedAggK<<<warpBlk_NF, 256, 0, s2>>>(offB, srcB, (const float4*)as2B, as2B,
                                          (const float4*)ad2B, hsB, biasNF + DIM,
                                          (float4*)out_food, NF);
    cudaEventRecord(eB1, s2);

    // ---- join ----
    cudaStreamWaitEvent(0, eB1, 0);
}

// round 14
// speedup vs baseline: 1.4173x; 1.0629x over previous
#include <cuda_runtime.h>
#include <cuda_fp16.h>
#include <mma.h>
#include <math.h>
#include <limits.h>

using namespace nvcuda;

#define DIM 128
#define NH 4
#define MAXN 50048
#define MAXE 800032
#define MAXDEG 96
#define SCANB 256
#define BCOLS 144      // 128 W cols + 4 v + 4 u + 8 pad
#define BSTRIDE 152    // smem ldm (halves)
#define CSTRIDE 148    // smem ldm (floats)

// ---------------- scratch (static device globals; no allocation) ----------------
__device__ __half g_hsA[MAXN * DIM];
__device__ __half g_hsB[MAXN * DIM];
__device__ __half g_Whx[4 * DIM * BCOLS];  // [side*2+l][128][144]
__device__ float g_hfood[MAXN * DIM];
__device__ float g_hnut[MAXN * DIM];
__device__ float g_asA[MAXN * NH];
__device__ float g_adA[MAXN * NH];
__device__ float g_asB[MAXN * NH];
__device__ float g_adB[MAXN * NH];
__device__ float g_as2A[MAXN * NH];
__device__ float g_ad2A[MAXN * NH];
__device__ float g_as2B[MAXN * NH];
__device__ float g_ad2B[MAXN * NH];
__device__ int   g_deg[2 * MAXN];     // zero-init; re-zeroed by sortZK epilogue
__device__ int   g_cur[2 * MAXN];
__device__ int   g_bsum[2 * 256];
__device__ int   g_offA[MAXN + 1];
__device__ int   g_offB[MAXN + 1];
__device__ int   g_srcA[MAXE];
__device__ int   g_srcB[MAXE];

// ---------------- CSR build ----------------
__global__ void histK(const int* __restrict__ dst, int* __restrict__ deg, int E) {
    int i = blockIdx.x * blockDim.x + threadIdx.x;
    int stride = gridDim.x * blockDim.x;
    for (; i < E; i += stride) atomicAdd(&deg[dst[i]], 1);
}

__global__ void scanSumK(const int* __restrict__ deg, int* __restrict__ bsum, int n) {
    __shared__ int wsum[8];
    int t = threadIdx.x;
    int i = blockIdx.x * SCANB + t;
    int v = (i < n) ? deg[i] : 0;
    #pragma unroll
    for (int o = 16; o > 0; o >>= 1) v += __shfl_down_sync(0xffffffffu, v, o);
    if ((t & 31) == 0) wsum[t >> 5] = v;
    __syncthreads();
    if (t == 0) {
        int s = 0;
        #pragma unroll
        for (int w = 0; w < 8; w++) s += wsum[w];
        bsum[blockIdx.x] = s;
    }
}

__global__ void scanApplyK(const int* __restrict__ deg, const int* __restrict__ bsum,
                           int* __restrict__ off, int* __restrict__ cur, int n) {
    __shared__ int wsum[8];
    __shared__ int shBase;
    int t = threadIdx.x;
    int lane = t & 31, wid = t >> 5;
    if (wid == 0) {
        int s = 0;
        for (int j = lane; j < blockIdx.x; j += 32) s += bsum[j];
        #pragma unroll
        for (int o = 16; o > 0; o >>= 1) s += __shfl_down_sync(0xffffffffu, s, o);
        if (lane == 0) shBase = s;
    }
    int i = blockIdx.x * SCANB + t;
    int v = (i < n) ? deg[i] : 0;
    int incl = v;
    #pragma unroll
    for (int o = 1; o < 32; o <<= 1) {
        int x = __shfl_up_sync(0xffffffffu, incl, o);
        if (lane >= o) incl += x;
    }
    if (lane == 31) wsum[wid] = incl;
    __syncthreads();
    if (wid == 0 && lane < 8) {
        int w = wsum[lane];
        int wi = w;
        #pragma unroll
        for (int o = 1; o < 8; o <<= 1) {
            int x = __shfl_up_sync(0xffu, wi, o);
            if (lane >= o) wi += x;
        }
        wsum[lane] = wi - w;
    }
    __syncthreads();
    int excl = incl - v + wsum[wid] + shBase;
    if (i < n) {
        off[i] = excl;
        cur[i] = excl;
        if (i == n - 1) off[n] = excl + v;
    }
}

__global__ void fillK(const int* __restrict__ ei, int* __restrict__ cur,
                      int* __restrict__ csrc, int E) {
    int i = blockIdx.x * blockDim.x + threadIdx.x;
    int stride = gridDim.x * blockDim.x;
    for (; i < E; i += stride) {
        int pos = atomicAdd(&cur[ei[E + i]], 1);
        csrc[pos] = ei[i];
    }
}

__global__ void __launch_bounds__(256)
sortZK(const int* __restrict__ off, int* __restrict__ csrc, int n,
       int* __restrict__ deg) {
    for (int i = blockIdx.x * blockDim.x + threadIdx.x; i < n;
         i += gridDim.x * blockDim.x) deg[i] = 0;

    int w = (blockIdx.x * blockDim.x + threadIdx.x) >> 5;
    int lane = threadIdx.x & 31;
    if (w >= n) return;
    int beg = off[w];
    int cnt = off[w + 1] - beg;
    if (cnt <= 1) return;
    if (cnt <= 32) {
        int v0 = (lane < cnt) ? csrc[beg + lane] : INT_MAX;
        #pragma unroll
        for (int size = 2; size <= 32; size <<= 1) {
            #pragma unroll
            for (int stride = size >> 1; stride > 0; stride >>= 1) {
                int p0 = __shfl_xor_sync(0xffffffffu, v0, stride);
                bool up0 = (size == 32) ? true : ((lane & size) == 0);
                bool lower = ((lane & stride) == 0);
                v0 = (lower == up0) ? min(v0, p0) : max(v0, p0);
            }
        }
        if (lane < cnt) csrc[beg + lane] = v0;
    } else if (cnt <= 64) {
        int v0 = (lane < cnt) ? csrc[beg + lane] : INT_MAX;
        int v1 = (32 + lane < cnt) ? csrc[beg + 32 + lane] : INT_MAX;
        #pragma unroll
        for (int size = 2; size <= 64; size <<= 1) {
            #pragma unroll
            for (int stride = size >> 1; stride > 0; stride >>= 1) {
                if (stride == 32) {
                    int lo = min(v0, v1), hi = max(v0, v1);
                    v0 = lo; v1 = hi;
                } else {
                    int p0 = __shfl_xor_sync(0xffffffffu, v0, stride);
                    int p1 = __shfl_xor_sync(0xffffffffu, v1, stride);
                    bool up0, up1;
                    if (size == 64)      { up0 = true; up1 = true; }
                    else if (size == 32) { up0 = true; up1 = false; }
                    else { up0 = ((lane & size) == 0); up1 = up0; }
                    bool lower = ((lane & stride) == 0);
                    v0 = (lower == up0) ? min(v0, p0) : max(v0, p0);
                    v1 = (lower == up1) ? min(v1, p1) : max(v1, p1);
                }
            }
        }
        if (lane < cnt) csrc[beg + lane] = v0;
        if (32 + lane < cnt) csrc[beg + 32 + lane] = v1;
    } else if (lane == 0) {
        int end = beg + cnt;
        for (int i = beg + 1; i < end; i++) {
            int key = csrc[i];
            int j = i - 1;
            while (j >= beg && csrc[j] > key) { csrc[j + 1] = csrc[j]; j--; }
            csrc[j + 1] = key;
        }
    }
}

// ---------------- extended fp16 weight pack: [Wsrc | v | u | 0] (uv fold inline) ----------------
__global__ void convWxK(const float* __restrict__ WsrcFN, const float* __restrict__ WdstFN,
                        const float* __restrict__ aSrcFN, const float* __restrict__ aDstFN,
                        const float* __restrict__ WsrcNF, const float* __restrict__ WdstNF,
                        const float* __restrict__ aSrcNF, const float* __restrict__ aDstNF,
                        __half* __restrict__ Whx) {
    int i = blockIdx.x * blockDim.x + threadIdx.x;
    if (i >= 4 * DIM * BCOLS) return;
    int mat = i / (DIM * BCOLS);     // side*2 + l
    int rem = i % (DIM * BCOLS);
    int k = rem / BCOLS;
    int c = rem % BCOLS;
    int side = mat >> 1, l = mat & 1;
    float val = 0.f;
    if (c < 128) {
        const float* W = side ? WsrcNF : WsrcFN;
        val = W[l * DIM * DIM + k * DIM + c];
    } else if (c < 136) {
        int h = (c - 128) & 3;
        int svsel = (c - 128) >> 2;  // 0 = v (src fold, own rel), 1 = u (dst fold, other rel)
        const float *W, *att;
        if (svsel == 0) {
            W = side ? WsrcNF : WsrcFN;
            att = side ? aSrcNF : aSrcFN;
        } else {
            W = side ? WdstFN : WdstNF;
            att = side ? aDstFN : aDstNF;
        }
        const float* Wl = W + l * DIM * DIM + k * DIM + h * 32;
        const float* al = att + l * NH * 32 + h * 32;
        float s = 0.f;
        #pragma unroll 8
        for (int cc = 0; cc < 32; cc++) s += Wl[cc] * al[cc];
        val = s;
    }
    Whx[i] = __float2half(val);
}

// ---------------- pipelined tensor-core GEMM + fused alpha projections ----------------
// Separate a/c smem buffers (no union); next-tile A prefetched into registers
// during MMA; 2 barriers per tile.
__global__ void __launch_bounds__(256)
gemmTC(const float* __restrict__ A, const __half* __restrict__ Whx,
       __half* __restrict__ C, float4* __restrict__ asOut, float4* __restrict__ adOut,
       int M, int numTiles) {
    __shared__ __half bsm[128 * BSTRIDE];
    __shared__ __half asmem[64 * 136];
    __shared__ float csm[64 * CSTRIDE];
    int t = threadIdx.x;

    // stage Whx (128 x 144 fp16): 18 uint4/row, 2 threads/row x 9
    {
        int r = t >> 1;
        int hv = t & 1;
        const uint4* src = (const uint4*)(Whx + (t >> 1) * BCOLS) + hv * 9;
        uint4* dst = (uint4*)(&bsm[r * BSTRIDE]) + hv * 9;
        #pragma unroll
        for (int i = 0; i < 9; i++) dst[i] = src[i];
    }

    int warpId = t >> 5;
    int wr = warpId & 3;
    int wc = warpId >> 2;          // 0: cols 0..79 (5 tiles), 1: cols 80..143 (4 tiles)
    int r = t >> 2;
    int c0 = (t & 3) * 32;

    // prologue: prefetch first tile's A rows into registers
    int tile = blockIdx.x;
    float4 regs[8];
    {
        int gr = tile * 64 + r;
        if (tile < numTiles && gr < M) {
            const float4* src = (const float4*)(A + (size_t)gr * DIM + c0);
            #pragma unroll
            for (int i = 0; i < 8; i++) regs[i] = src[i];
        }
    }

    for (; tile < numTiles; tile += gridDim.x) {
        int rowBase = tile * 64;
        int gr = rowBase + r;
        bool v = (gr < M);

        // step 1: store prefetched A (fp32->fp16) into smem
        {
            __half* dst = &asmem[r * 136 + c0];
            if (v) {
                #pragma unroll
                for (int i = 0; i < 8; i++) {
                    float4 x = regs[i];
                    *(__half2*)(dst + i * 4)     = __floats2half2_rn(x.x, x.y);
                    *(__half2*)(dst + i * 4 + 2) = __floats2half2_rn(x.z, x.w);
                }
            } else {
                #pragma unroll
                for (int i = 0; i < 8; i++) {
                    *(__half2*)(dst + i * 4)     = __half2half2(__float2half(0.f));
                    *(__half2*)(dst + i * 4 + 2) = __half2half2(__float2half(0.f));
                }
            }
        }
        __syncthreads();   // A (and, first iter, W) staged; prior csm writeback done

        // step 3: prefetch NEXT tile's A (LDG latency hides under MMA)
        {
            int nt = tile + gridDim.x;
            int ngr = nt * 64 + r;
            if (nt < numTiles && ngr < M) {
                const float4* src = (const float4*)(A + (size_t)ngr * DIM + c0);
                #pragma unroll
                for (int i = 0; i < 8; i++) regs[i] = src[i];
            }
        }

        // step 4: MMA
        wmma::fragment<wmma::accumulator, 16, 16, 16, float> cf[5];
        #pragma unroll
        for (int j = 0; j < 5; j++) wmma::fill_fragment(cf[j], 0.f);

        if (wc == 0) {
            #pragma unroll
            for (int k0 = 0; k0 < 8; k0++) {
                wmma::fragment<wmma::matrix_a, 16, 16, 16, __half, wmma::row_major> af;
                wmma::load_matrix_sync(af, &asmem[(wr * 16) * 136 + k0 * 16], 136);
                #pragma unroll
                for (int j = 0; j < 5; j++) {
                    wmma::fragment<wmma::matrix_b, 16, 16, 16, __half, wmma::row_major> bf;
                    wmma::load_matrix_sync(bf, &bsm[(k0 * 16) * BSTRIDE + j * 16], BSTRIDE);
                    wmma::mma_sync(cf[j], af, bf, cf[j]);
                }
            }
            #pragma unroll
            for (int j = 0; j < 5; j++)
                wmma::store_matrix_sync(&csm[(wr * 16) * CSTRIDE + j * 16], cf[j],
                                        CSTRIDE, wmma::mem_row_major);
        } else {
            #pragma unroll
            for (int k0 = 0; k0 < 8; k0++) {
                wmma::fragment<wmma::matrix_a, 16, 16, 16, __half, wmma::row_major> af;
                wmma::load_matrix_sync(af, &asmem[(wr * 16) * 136 + k0 * 16], 136);
                #pragma unroll
                for (int j = 0; j < 4; j++) {
                    wmma::fragment<wmma::matrix_b, 16, 16, 16, __half, wmma::row_major> bf;
                    wmma::load_matrix_sync(bf, &bsm[(k0 * 16) * BSTRIDE + 80 + j * 16], BSTRIDE);
                    wmma::mma_sync(cf[j], af, bf, cf[j]);
                }
            }
            #pragma unroll
            for (int j = 0; j < 4; j++)
                wmma::store_matrix_sync(&csm[(wr * 16) * CSTRIDE + 80 + j * 16], cf[j],
                                        CSTRIDE, wmma::mem_row_major);
        }
        __syncthreads();   // MMA + csm stores complete

        // step 7: writeback h (fp16) + alphas (fp32)
        if (v) {
            const float* src = &csm[r * CSTRIDE + c0];
            __half2* dst = (__half2*)(C + (size_t)gr * DIM + c0);
            #pragma unroll
            for (int i = 0; i < 16; i++)
                dst[i] = __floats2half2_rn(src[2 * i], src[2 * i + 1]);
            if ((t & 3) == 0) {
                asOut[gr] = *(const float4*)(&csm[r * CSTRIDE + 128]);
                adOut[gr] = *(const float4*)(&csm[r * CSTRIDE + 132]);
            }
        }
    }
}

// ---------------- fused softmax-stats + aggregation + bias + ELU ----------------
__global__ void __launch_bounds__(256)
fusedAggK(const int* __restrict__ off, const int* __restrict__ csrc,
          const float4* __restrict__ as4, const float* __restrict__ as1,
          const float4* __restrict__ ad,
          const __half* __restrict__ hs, const float* __restrict__ bias,
          float4* __restrict__ out, int n) {
    __shared__ float see[8][MAXDEG][4];
    __shared__ int ssrc[8][MAXDEG];
    int w = threadIdx.x >> 5;
    int lane = threadIdx.x & 31;
    int d = blockIdx.x * 8 + w;
    if (d >= n) return;

    int beg = off[d], end = off[d + 1];
    int deg = end - beg;
    bool cached = (deg <= MAXDEG);

    float4 adv = ad[d];
    float adh4[4] = {adv.x, adv.y, adv.z, adv.w};
    float m[4] = {-1e30f, -1e30f, -1e30f, -1e30f};
    float s[4] = {0.f, 0.f, 0.f, 0.f};

    for (int i = lane; i < deg; i += 32) {
        int src = csrc[beg + i];
        float4 av = as4[src];
        float ev[4] = {av.x + adh4[0], av.y + adh4[1], av.z + adh4[2], av.w + adh4[3]};
        float ee[4];
        #pragma unroll
        for (int h = 0; h < 4; h++) {
            float e = ev[h] > 0.f ? ev[h] : 0.2f * ev[h];
            ee[h] = e;
            if (e > m[h]) {
                s[h] = s[h] * __expf(m[h] - e) + 1.f;
                m[h] = e;
            } else {
                s[h] += __expf(e - m[h]);
            }
        }
        if (cached) {
            ssrc[w][i] = src;
            *(float4*)(&see[w][i][0]) = make_float4(ee[0], ee[1], ee[2], ee[3]);
        }
    }
    #pragma unroll
    for (int o = 16; o > 0; o >>= 1) {
        #pragma unroll
        for (int h = 0; h < 4; h++) {
            float om = __shfl_xor_sync(0xffffffffu, m[h], o);
            float os = __shfl_xor_sync(0xffffffffu, s[h], o);
            float nm = fmaxf(m[h], om);
            s[h] = s[h] * __expf(m[h] - nm) + os * __expf(om - nm);
            m[h] = nm;
        }
    }
    float rAll[4];
    #pragma unroll
    for (int h = 0; h < 4; h++) rAll[h] = 1.f / (s[h] + 1e-16f);

    if (cached) {
        for (int i = lane; i < deg; i += 32) {
            float4 e4 = *(float4*)(&see[w][i][0]);
            e4.x = __expf(e4.x - m[0]) * rAll[0];
            e4.y = __expf(e4.y - m[1]) * rAll[1];
            e4.z = __expf(e4.z - m[2]) * rAll[2];
            e4.w = __expf(e4.w - m[3]) * rAll[3];
            *(float4*)(&see[w][i][0]) = e4;
        }
    }
    __syncwarp();

    int h = lane >> 3;
    float mh = m[h];
    float rh = rAll[h];
    float adh = adh4[h];

    float4 acc = make_float4(0.f, 0.f, 0.f, 0.f);
    for (int e = 0; e < deg; e++) {
        int src;
        float wgt;
        if (cached) {
            src = ssrc[w][e];
            wgt = see[w][e][h];
        } else {
            src = csrc[beg + e];
            float a = __ldg(&as1[src * 4 + h]);
            float ev = a + adh;
            float ee = ev > 0.f ? ev : 0.2f * ev;
            wgt = __expf(ee - mh) * rh;
        }
        const __half2* hp = reinterpret_cast<const __half2*>(hs + src * DIM) + lane * 2;
        __half2 p0 = hp[0], p1 = hp[1];
        float2 f0 = __half22float2(p0);
        float2 f1 = __half22float2(p1);
        acc.x += wgt * f0.x;
        acc.y += wgt * f0.y;
        acc.z += wgt * f1.x;
        acc.w += wgt * f1.y;
    }
    float4 b = *(const float4*)(bias + lane * 4);
    acc.x += b.x; acc.y += b.y; acc.z += b.z; acc.w += b.w;
    acc.x = acc.x > 0.f ? acc.x : expm1f(acc.x);
    acc.y = acc.y > 0.f ? acc.y : expm1f(acc.y);
    acc.z = acc.z > 0.f ? acc.z : expm1f(acc.z);
    acc.w = acc.w > 0.f ? acc.w : expm1f(acc.w);
    out[d * 32 + lane] = acc;
}

// ---------------- driver ----------------
extern "C" void kernel_launch(void* const* d_in, const int* in_sizes, int n_in,
                              void* d_out, int out_size) {
    const float* x_food  = (const float*)d_in[0];
    const float* x_nut   = (const float*)d_in[1];
    const float* WsrcFN  = (const float*)d_in[2];
    const float* WdstFN  = (const float*)d_in[3];
    const float* aSrcFN  = (const float*)d_in[4];
    const float* aDstFN  = (const float*)d_in[5];
    const float* biasFN  = (const float*)d_in[6];
    const float* WsrcNF  = (const float*)d_in[7];
    const float* WdstNF  = (const float*)d_in[8];
    const float* aSrcNF  = (const float*)d_in[9];
    const float* aDstNF  = (const float*)d_in[10];
    const float* biasNF  = (const float*)d_in[11];
    const int*   ei_fn   = (const int*)d_in[12];
    const int*   ei_nf   = (const int*)d_in[13];
    float* out = (float*)d_out;

    int NF = in_sizes[0] / DIM;
    int NN = in_sizes[1] / DIM;
    int E  = in_sizes[12] / 2;

    __half *hsA, *hsB, *Whx;
    float *hfood, *hnut, *asA, *adA, *asB, *adB, *as2A, *ad2A, *as2B, *ad2B;
    int *deg, *cur, *bsum, *offA, *offB, *srcA, *srcB;
    cudaGetSymbolAddress((void**)&hsA, g_hsA);
    cudaGetSymbolAddress((void**)&hsB, g_hsB);
    cudaGetSymbolAddress((void**)&Whx, g_Whx);
    cudaGetSymbolAddress((void**)&hfood, g_hfood);
    cudaGetSymbolAddress((void**)&hnut, g_hnut);
    cudaGetSymbolAddress((void**)&asA, g_asA);
    cudaGetSymbolAddress((void**)&adA, g_adA);
    cudaGetSymbolAddress((void**)&asB, g_asB);
    cudaGetSymbolAddress((void**)&adB, g_adB);
    cudaGetSymbolAddress((void**)&as2A, g_as2A);
    cudaGetSymbolAddress((void**)&ad2A, g_ad2A);
    cudaGetSymbolAddress((void**)&as2B, g_as2B);
    cudaGetSymbolAddress((void**)&ad2B, g_ad2B);
    cudaGetSymbolAddress((void**)&deg, g_deg);
    cudaGetSymbolAddress((void**)&cur, g_cur);
    cudaGetSymbolAddress((void**)&bsum, g_bsum);
    cudaGetSymbolAddress((void**)&offA, g_offA);
    cudaGetSymbolAddress((void**)&offB, g_offB);
    cudaGetSymbolAddress((void**)&srcA, g_srcA);
    cudaGetSymbolAddress((void**)&srcB, g_srcB);

    int* degA = deg;
    int* degB = deg + MAXN;
    int* curA = cur;
    int* curB = cur + MAXN;
    int* bsumA = bsum;
    int* bsumB = bsum + 256;

    int warpBlk_NN = (NN + 7) / 8;
    int warpBlk_NF = (NF + 7) / 8;
    int gemmTiles_NF = (NF + 63) / 64;
    int gemmTiles_NN = (NN + 63) / 64;
    const int GEMM_GRID = 296;
    int scanBlkA = (NN + SCANB - 1) / SCANB;
    int scanBlkB = (NF + SCANB - 1) / SCANB;

    static cudaStream_t s1 = nullptr, s2 = nullptr, s3 = nullptr;
    static cudaEvent_t eR, eCW, eG0A, eG0B, eCA, eB0, eA0, eG1A, eG1B, eB1;
    if (!s1) {
        cudaStreamCreateWithFlags(&s1, cudaStreamNonBlocking);
        cudaStreamCreateWithFlags(&s2, cudaStreamNonBlocking);
        cudaStreamCreateWithFlags(&s3, cudaStreamNonBlocking);
        cudaEventCreateWithFlags(&eR,   cudaEventDisableTiming);
        cudaEventCreateWithFlags(&eCW,  cudaEventDisableTiming);
        cudaEventCreateWithFlags(&eG0A, cudaEventDisableTiming);
        cudaEventCreateWithFlags(&eG0B, cudaEventDisableTiming);
        cudaEventCreateWithFlags(&eCA,  cudaEventDisableTiming);
        cudaEventCreateWithFlags(&eB0,  cudaEventDisableTiming);
        cudaEventCreateWithFlags(&eA0,  cudaEventDisableTiming);
        cudaEventCreateWithFlags(&eG1A, cudaEventDisableTiming);
        cudaEventCreateWithFlags(&eG1B, cudaEventDisableTiming);
        cudaEventCreateWithFlags(&eB1,  cudaEventDisableTiming);
    }

    const __half* Whx_f0 = Whx + 0 * DIM * BCOLS;  // food, layer 0
    const __half* Whx_f1 = Whx + 1 * DIM * BCOLS;  // food, layer 1
    const __half* Whx_n0 = Whx + 2 * DIM * BCOLS;  // nut, layer 0
    const __half* Whx_n1 = Whx + 3 * DIM * BCOLS;  // nut, layer 1
    float* out_food = out;
    float* out_nut  = out + (size_t)NF * DIM;

    // ---- fork ----
    cudaEventRecord(eR, 0);
    cudaStreamWaitEvent(s1, eR, 0);
    cudaStreamWaitEvent(s2, eR, 0);
    cudaStreamWaitEvent(s3, eR, 0);

    // S0: pack extended fp16 weights (uv fold inline), layer-0 food GEMM
    convWxK<<<(4 * DIM * BCOLS + 255) / 256, 256>>>(WsrcFN, WdstFN, aSrcFN, aDstFN,
                                                    WsrcNF, WdstNF, aSrcNF, aDstNF, Whx);
    cudaEventRecord(eCW, 0);
    gemmTC<<<GEMM_GRID, 256>>>(x_food, Whx_f0, hsA, (float4*)asA, (float4*)adB,
                               NF, gemmTiles_NF);
    cudaEventRecord(eG0A, 0);

    // S3: layer-0 nut GEMM (parallel with CSR builds)
    cudaStreamWaitEvent(s3, eCW, 0);
    gemmTC<<<GEMM_GRID, 256, 0, s3>>>(x_nut, Whx_n0, hsB, (float4*)asB, (float4*)adA,
                                      NN, gemmTiles_NN);
    cudaEventRecord(eG0B, s3);

    // S1: CSR-A
    histK<<<1024, 256, 0, s1>>>(ei_fn + E, degA, E);
    scanSumK<<<scanBlkA, SCANB, 0, s1>>>(degA, bsumA, NN);
    scanApplyK<<<scanBlkA, SCANB, 0, s1>>>(degA, bsumA, offA, curA, NN);
    fillK<<<1024, 256, 0, s1>>>(ei_fn, curA, srcA, E);
    sortZK<<<(NN + 7) / 8, 256, 0, s1>>>(offA, srcA, NN, degA);
    cudaEventRecord(eCA, s1);

    // S2: CSR-B
    histK<<<1024, 256, 0, s2>>>(ei_nf + E, degB, E);
    scanSumK<<<scanBlkB, SCANB, 0, s2>>>(degB, bsumB, NF);
    scanApplyK<<<scanBlkB, SCANB, 0, s2>>>(degB, bsumB, offB, curB, NF);
    fillK<<<1024, 256, 0, s2>>>(ei_nf, curB, srcB, E);
    sortZK<<<(NF + 7) / 8, 256, 0, s2>>>(offB, srcB, NF, degB);

    // S2: layer-0 nf agg (asB from gemm0B, adB from gemm0A, hsB) -> hfood
    cudaStreamWaitEvent(s2, eG0A, 0);
    cudaStreamWaitEvent(s2, eG0B, 0);
    fusedAggK<<<warpBlk_NF, 256, 0, s2>>>(offB, srcB, (const float4*)asB, asB,
                                          (const float4*)adB, hsB, biasNF,
                                          (float4*)hfood, NF);
    cudaEventRecord(eB0, s2);

    // S0: layer-0 fn agg (asA from gemm0A, adA from gemm0B, hsA) -> hnut
    cudaStreamWaitEvent(0, eCA, 0);
    cudaStreamWaitEvent(0, eG0B, 0);
    fusedAggK<<<warpBlk_NN, 256>>>(offA, srcA, (const float4*)asA, asA,
                                   (const float4*)adA, hsA, biasFN,
                                   (float4*)hnut, NN);
    cudaEventRecord(eA0, 0);

    // S0: layer-1 food GEMM (hfood -> hsA, as2A, ad2B)
    cudaStreamWaitEvent(0, eB0, 0);
    gemmTC<<<GEMM_GRID, 256>>>(hfood, Whx_f1, hsA, (float4*)as2A, (float4*)ad2B,
                               NF, gemmTiles_NF);
    cudaEventRecord(eG1A, 0);

    // S2: layer-1 nut GEMM (hnut -> hsB, as2B, ad2A)
    cudaStreamWaitEvent(s2, eA0, 0);
    gemmTC<<<GEMM_GRID, 256, 0, s2>>>(hnut, Whx_n1, hsB, (float4*)as2B, (float4*)ad2A,
                                      NN, gemmTiles_NN);
    cudaEventRecord(eG1B, s2);

    // S0: layer-1 fn agg (as2A from gemm1A, ad2A from gemm1B) -> out_nut
    cudaStreamWaitEvent(0, eG1B, 0);
    fusedAggK<<<warpBlk_NN, 256>>>(offA, srcA, (const float4*)as2A, as2A,
                                   (const float4*)ad2A, hsA, biasFN + DIM,
                                   (float4*)out_nut, NN);

    // S2: layer-1 nf agg (as2B from gemm1B, ad2B from gemm1A) -> out_food
    cudaStreamWaitEvent(s2, eG1A, 0);
    fusedAggK<<<warpBlk_NF, 256, 0, s2>>>(offB, srcB, (const float4*)as2B, as2B,
                                          (const float4*)ad2B, hsB, biasNF + DIM,
                                          (float4*)out_food, NF);
    cudaEventRecord(eB1, s2);

    // ---- join ----
    cudaStreamWaitEvent(0, eB1, 0);
}

// round 15
// speedup vs baseline: 1.5356x; 1.0835x over previous
#include <cuda_runtime.h>
#include <cuda_fp16.h>
#include <mma.h>
#include <math.h>
#include <limits.h>

using namespace nvcuda;

#define DIM 128
#define NH 4
#define MAXN 50048
#define MAXE 800032
#define MAXDEG 96
#define SCANB 256
#define BCOLS 144      // 128 W cols + 4 v + 4 u + 8 pad
#define BSTRIDE 152    // smem ldm (halves)
#define CSTRIDE 148    // smem ldm (floats)

// ---------------- scratch (static device globals; no allocation) ----------------
__device__ __half g_hsA[MAXN * DIM];
__device__ __half g_hsB[MAXN * DIM];
__device__ __half g_Whx[4 * DIM * BCOLS];  // [side*2+l][128][144]
__device__ float g_hfood[MAXN * DIM];
__device__ float g_hnut[MAXN * DIM];
__device__ float g_asA[MAXN * NH];
__device__ float g_adA[MAXN * NH];
__device__ float g_asB[MAXN * NH];
__device__ float g_adB[MAXN * NH];
__device__ float g_as2A[MAXN * NH];
__device__ float g_ad2A[MAXN * NH];
__device__ float g_as2B[MAXN * NH];
__device__ float g_ad2B[MAXN * NH];
__device__ int   g_deg[2 * MAXN];     // zero-init; re-zeroed by sortZ2K epilogue
__device__ int   g_cur[2 * MAXN];
__device__ int   g_bsum[2 * 256];
__device__ int   g_offA[MAXN + 1];
__device__ int   g_offB[MAXN + 1];
__device__ int   g_srcA[MAXE];
__device__ int   g_srcB[MAXE];

// ---------------- CSR build (both relations per kernel) ----------------
__global__ void hist2K(const int* __restrict__ eiA, const int* __restrict__ eiB,
                       int* __restrict__ degA, int* __restrict__ degB, int E) {
    int i = blockIdx.x * blockDim.x + threadIdx.x;
    int stride = gridDim.x * blockDim.x;
    for (; i < 2 * E; i += stride) {
        if (i < E) atomicAdd(&degA[eiA[E + i]], 1);
        else       atomicAdd(&degB[eiB[E + (i - E)]], 1);
    }
}

__global__ void scanSum2K(const int* __restrict__ degA, int* __restrict__ bsumA, int nA,
                          const int* __restrict__ degB, int* __restrict__ bsumB, int nB,
                          int blkA) {
    __shared__ int wsum[8];
    int t = threadIdx.x;
    const int* deg;
    int* bsum;
    int n, b;
    if (blockIdx.x < blkA) { deg = degA; bsum = bsumA; n = nA; b = blockIdx.x; }
    else                   { deg = degB; bsum = bsumB; n = nB; b = blockIdx.x - blkA; }
    int i = b * SCANB + t;
    int v = (i < n) ? deg[i] : 0;
    #pragma unroll
    for (int o = 16; o > 0; o >>= 1) v += __shfl_down_sync(0xffffffffu, v, o);
    if ((t & 31) == 0) wsum[t >> 5] = v;
    __syncthreads();
    if (t == 0) {
        int s = 0;
        #pragma unroll
        for (int w = 0; w < 8; w++) s += wsum[w];
        bsum[b] = s;
    }
}

__global__ void scanApply2K(const int* __restrict__ degA, const int* __restrict__ bsumA,
                            int* __restrict__ offA, int* __restrict__ curA, int nA,
                            const int* __restrict__ degB, const int* __restrict__ bsumB,
                            int* __restrict__ offB, int* __restrict__ curB, int nB,
                            int blkA) {
    __shared__ int wsum[8];
    __shared__ int shBase;
    int t = threadIdx.x;
    int lane = t & 31, wid = t >> 5;
    const int *deg, *bsum;
    int *off, *cur;
    int n, b;
    if (blockIdx.x < blkA) { deg = degA; bsum = bsumA; off = offA; cur = curA; n = nA; b = blockIdx.x; }
    else                   { deg = degB; bsum = bsumB; off = offB; cur = curB; n = nB; b = blockIdx.x - blkA; }
    if (wid == 0) {
        int s = 0;
        for (int j = lane; j < b; j += 32) s += bsum[j];
        #pragma unroll
        for (int o = 16; o > 0; o >>= 1) s += __shfl_down_sync(0xffffffffu, s, o);
        if (lane == 0) shBase = s;
    }
    int i = b * SCANB + t;
    int v = (i < n) ? deg[i] : 0;
    int incl = v;
    #pragma unroll
    for (int o = 1; o < 32; o <<= 1) {
        int x = __shfl_up_sync(0xffffffffu, incl, o);
        if (lane >= o) incl += x;
    }
    if (lane == 31) wsum[wid] = incl;
    __syncthreads();
    if (wid == 0 && lane < 8) {
        int w = wsum[lane];
        int wi = w;
        #pragma unroll
        for (int o = 1; o < 8; o <<= 1) {
            int x = __shfl_up_sync(0xffu, wi, o);
            if (lane >= o) wi += x;
        }
        wsum[lane] = wi - w;
    }
    __syncthreads();
    int excl = incl - v + wsum[wid] + shBase;
    if (i < n) {
        off[i] = excl;
        cur[i] = excl;
        if (i == n - 1) off[n] = excl + v;
    }
}

__global__ void fill2K(const int* __restrict__ eiA, const int* __restrict__ eiB,
                       int* __restrict__ curA, int* __restrict__ curB,
                       int* __restrict__ srcA, int* __restrict__ srcB, int E) {
    int i = blockIdx.x * blockDim.x + threadIdx.x;
    int stride = gridDim.x * blockDim.x;
    for (; i < 2 * E; i += stride) {
        if (i < E) {
            int pos = atomicAdd(&curA[eiA[E + i]], 1);
            srcA[pos] = eiA[i];
        } else {
            int j = i - E;
            int pos = atomicAdd(&curB[eiB[E + j]], 1);
            srcB[pos] = eiB[j];
        }
    }
}

__global__ void __launch_bounds__(256)
sortZ2K(const int* __restrict__ offA, int* __restrict__ srcA, int nA,
        const int* __restrict__ offB, int* __restrict__ srcB, int nB,
        int* __restrict__ deg2) {
    for (int i = blockIdx.x * blockDim.x + threadIdx.x; i < 2 * MAXN;
         i += gridDim.x * blockDim.x) deg2[i] = 0;

    int w = (blockIdx.x * blockDim.x + threadIdx.x) >> 5;
    int lane = threadIdx.x & 31;
    const int* off;
    int* csrc;
    if (w < nA) { off = offA; csrc = srcA; }
    else if (w < nA + nB) { off = offB; csrc = srcB; w -= nA; }
    else return;
    int beg = off[w];
    int cnt = off[w + 1] - beg;
    if (cnt <= 1) return;
    if (cnt <= 32) {
        int v0 = (lane < cnt) ? csrc[beg + lane] : INT_MAX;
        #pragma unroll
        for (int size = 2; size <= 32; size <<= 1) {
            #pragma unroll
            for (int stride = size >> 1; stride > 0; stride >>= 1) {
                int p0 = __shfl_xor_sync(0xffffffffu, v0, stride);
                bool up0 = (size == 32) ? true : ((lane & size) == 0);
                bool lower = ((lane & stride) == 0);
                v0 = (lower == up0) ? min(v0, p0) : max(v0, p0);
            }
        }
        if (lane < cnt) csrc[beg + lane] = v0;
    } else if (cnt <= 64) {
        int v0 = (lane < cnt) ? csrc[beg + lane] : INT_MAX;
        int v1 = (32 + lane < cnt) ? csrc[beg + 32 + lane] : INT_MAX;
        #pragma unroll
        for (int size = 2; size <= 64; size <<= 1) {
            #pragma unroll
            for (int stride = size >> 1; stride > 0; stride >>= 1) {
                if (stride == 32) {
                    int lo = min(v0, v1), hi = max(v0, v1);
                    v0 = lo; v1 = hi;
                } else {
                    int p0 = __shfl_xor_sync(0xffffffffu, v0, stride);
                    int p1 = __shfl_xor_sync(0xffffffffu, v1, stride);
                    bool up0, up1;
                    if (size == 64)      { up0 = true; up1 = true; }
                    else if (size == 32) { up0 = true; up1 = false; }
                    else { up0 = ((lane & size) == 0); up1 = up0; }
                    bool lower = ((lane & stride) == 0);
                    v0 = (lower == up0) ? min(v0, p0) : max(v0, p0);
                    v1 = (lower == up1) ? min(v1, p1) : max(v1, p1);
                }
            }
        }
        if (lane < cnt) csrc[beg + lane] = v0;
        if (32 + lane < cnt) csrc[beg + 32 + lane] = v1;
    } else if (lane == 0) {
        int end = beg + cnt;
        for (int i = beg + 1; i < end; i++) {
            int key = csrc[i];
            int j = i - 1;
            while (j >= beg && csrc[j] > key) { csrc[j + 1] = csrc[j]; j--; }
            csrc[j + 1] = key;
        }
    }
}

// ---------------- extended fp16 weight pack: [Wsrc | v | u | 0] (uv fold inline) ----------------
__global__ void convWxK(const float* __restrict__ WsrcFN, const float* __restrict__ WdstFN,
                        const float* __restrict__ aSrcFN, const float* __restrict__ aDstFN,
                        const float* __restrict__ WsrcNF, const float* __restrict__ WdstNF,
                        const float* __restrict__ aSrcNF, const float* __restrict__ aDstNF,
                        __half* __restrict__ Whx) {
    int i = blockIdx.x * blockDim.x + threadIdx.x;
    if (i >= 4 * DIM * BCOLS) return;
    int mat = i / (DIM * BCOLS);     // side*2 + l
    int rem = i % (DIM * BCOLS);
    int k = rem / BCOLS;
    int c = rem % BCOLS;
    int side = mat >> 1, l = mat & 1;
    float val = 0.f;
    if (c < 128) {
        const float* W = side ? WsrcNF : WsrcFN;
        val = W[l * DIM * DIM + k * DIM + c];
    } else if (c < 136) {
        int h = (c - 128) & 3;
        int svsel = (c - 128) >> 2;  // 0 = v (src fold, own rel), 1 = u (dst fold, other rel)
        const float *W, *att;
        if (svsel == 0) {
            W = side ? WsrcNF : WsrcFN;
            att = side ? aSrcNF : aSrcFN;
        } else {
            W = side ? WdstFN : WdstNF;
            att = side ? aDstFN : aDstNF;
        }
        const float* Wl = W + l * DIM * DIM + k * DIM + h * 32;
        const float* al = att + l * NH * 32 + h * 32;
        float s = 0.f;
        #pragma unroll 8
        for (int cc = 0; cc < 32; cc++) s += Wl[cc] * al[cc];
        val = s;
    }
    Whx[i] = __float2half(val);
}

// ---------------- pipelined tensor-core GEMM + fused alpha projections ----------------
__global__ void __launch_bounds__(256)
gemmTC(const float* __restrict__ A, const __half* __restrict__ Whx,
       __half* __restrict__ C, float4* __restrict__ asOut, float4* __restrict__ adOut,
       int M, int numTiles) {
    __shared__ __half bsm[128 * BSTRIDE];
    __shared__ __half asmem[64 * 136];
    __shared__ float csm[64 * CSTRIDE];
    int t = threadIdx.x;

    {
        int r = t >> 1;
        int hv = t & 1;
        const uint4* src = (const uint4*)(Whx + r * BCOLS) + hv * 9;
        uint4* dst = (uint4*)(&bsm[r * BSTRIDE]) + hv * 9;
        #pragma unroll
        for (int i = 0; i < 9; i++) dst[i] = src[i];
    }

    int warpId = t >> 5;
    int wr = warpId & 3;
    int wc = warpId >> 2;
    int r = t >> 2;
    int c0 = (t & 3) * 32;

    int tile = blockIdx.x;
    float4 regs[8];
    {
        int gr = tile * 64 + r;
        if (tile < numTiles && gr < M) {
            const float4* src = (const float4*)(A + (size_t)gr * DIM + c0);
            #pragma unroll
            for (int i = 0; i < 8; i++) regs[i] = src[i];
        }
    }

    for (; tile < numTiles; tile += gridDim.x) {
        int rowBase = tile * 64;
        int gr = rowBase + r;
        bool v = (gr < M);

        {
            __half* dst = &asmem[r * 136 + c0];
            if (v) {
                #pragma unroll
                for (int i = 0; i < 8; i++) {
                    float4 x = regs[i];
                    *(__half2*)(dst + i * 4)     = __floats2half2_rn(x.x, x.y);
                    *(__half2*)(dst + i * 4 + 2) = __floats2half2_rn(x.z, x.w);
                }
            } else {
                #pragma unroll
                for (int i = 0; i < 8; i++) {
                    *(__half2*)(dst + i * 4)     = __half2half2(__float2half(0.f));
                    *(__half2*)(dst + i * 4 + 2) = __half2half2(__float2half(0.f));
                }
            }
        }
        __syncthreads();

        {
            int nt = tile + gridDim.x;
            int ngr = nt * 64 + r;
            if (nt < numTiles && ngr < M) {
                const float4* src = (const float4*)(A + (size_t)ngr * DIM + c0);
                #pragma unroll
                for (int i = 0; i < 8; i++) regs[i] = src[i];
            }
        }

        wmma::fragment<wmma::accumulator, 16, 16, 16, float> cf[5];
        #pragma unroll
        for (int j = 0; j < 5; j++) wmma::fill_fragment(cf[j], 0.f);

        if (wc == 0) {
            #pragma unroll
            for (int k0 = 0; k0 < 8; k0++) {
                wmma::fragment<wmma::matrix_a, 16, 16, 16, __half, wmma::row_major> af;
                wmma::load_matrix_sync(af, &asmem[(wr * 16) * 136 + k0 * 16], 136);
                #pragma unroll
                for (int j = 0; j < 5; j++) {
                    wmma::fragment<wmma::matrix_b, 16, 16, 16, __half, wmma::row_major> bf;
                    wmma::load_matrix_sync(bf, &bsm[(k0 * 16) * BSTRIDE + j * 16], BSTRIDE);
                    wmma::mma_sync(cf[j], af, bf, cf[j]);
                }
            }
            #pragma unroll
            for (int j = 0; j < 5; j++)
                wmma::store_matrix_sync(&csm[(wr * 16) * CSTRIDE + j * 16], cf[j],
                                        CSTRIDE, wmma::mem_row_major);
        } else {
            #pragma unroll
            for (int k0 = 0; k0 < 8; k0++) {
                wmma::fragment<wmma::matrix_a, 16, 16, 16, __half, wmma::row_major> af;
                wmma::load_matrix_sync(af, &asmem[(wr * 16) * 136 + k0 * 16], 136);
                #pragma unroll
                for (int j = 0; j < 4; j++) {
                    wmma::fragment<wmma::matrix_b, 16, 16, 16, __half, wmma::row_major> bf;
                    wmma::load_matrix_sync(bf, &bsm[(k0 * 16) * BSTRIDE + 80 + j * 16], BSTRIDE);
                    wmma::mma_sync(cf[j], af, bf, cf[j]);
                }
            }
            #pragma unroll
            for (int j = 0; j < 4; j++)
                wmma::store_matrix_sync(&csm[(wr * 16) * CSTRIDE + 80 + j * 16], cf[j],
                                        CSTRIDE, wmma::mem_row_major);
        }
        __syncthreads();

        if (v) {
            const float* src = &csm[r * CSTRIDE + c0];
            __half2* dst = (__half2*)(C + (size_t)gr * DIM + c0);
            #pragma unroll
            for (int i = 0; i < 16; i++)
                dst[i] = __floats2half2_rn(src[2 * i], src[2 * i + 1]);
            if ((t & 3) == 0) {
                asOut[gr] = *(const float4*)(&csm[r * CSTRIDE + 128]);
                adOut[gr] = *(const float4*)(&csm[r * CSTRIDE + 132]);
            }
        }
    }
}

// ---------------- fused softmax-stats + aggregation + bias + ELU ----------------
__global__ void __launch_bounds__(256)
fusedAggK(const int* __restrict__ off, const int* __restrict__ csrc,
          const float4* __restrict__ as4, const float* __restrict__ as1,
          const float4* __restrict__ ad,
          const __half* __restrict__ hs, const float* __restrict__ bias,
          float4* __restrict__ out, int n) {
    __shared__ float see[8][MAXDEG][4];
    __shared__ int ssrc[8][MAXDEG];
    int w = threadIdx.x >> 5;
    int lane = threadIdx.x & 31;
    int d = blockIdx.x * 8 + w;
    if (d >= n) return;

    int beg = off[d], end = off[d + 1];
    int deg = end - beg;
    bool cached = (deg <= MAXDEG);

    float4 adv = ad[d];
    float adh4[4] = {adv.x, adv.y, adv.z, adv.w};
    float m[4] = {-1e30f, -1e30f, -1e30f, -1e30f};
    float s[4] = {0.f, 0.f, 0.f, 0.f};

    for (int i = lane; i < deg; i += 32) {
        int src = csrc[beg + i];
        float4 av = as4[src];
        float ev[4] = {av.x + adh4[0], av.y + adh4[1], av.z + adh4[2], av.w + adh4[3]};
        float ee[4];
        #pragma unroll
        for (int h = 0; h < 4; h++) {
            float e = ev[h] > 0.f ? ev[h] : 0.2f * ev[h];
            ee[h] = e;
            if (e > m[h]) {
                s[h] = s[h] * __expf(m[h] - e) + 1.f;
                m[h] = e;
            } else {
                s[h] += __expf(e - m[h]);
            }
        }
        if (cached) {
            ssrc[w][i] = src;
            *(float4*)(&see[w][i][0]) = make_float4(ee[0], ee[1], ee[2], ee[3]);
        }
    }
    #pragma unroll
    for (int o = 16; o > 0; o >>= 1) {
        #pragma unroll
        for (int h = 0; h < 4; h++) {
            float om = __shfl_xor_sync(0xffffffffu, m[h], o);
            float os = __shfl_xor_sync(0xffffffffu, s[h], o);
            float nm = fmaxf(m[h], om);
            s[h] = s[h] * __expf(m[h] - nm) + os * __expf(om - nm);
            m[h] = nm;
        }
    }
    float rAll[4];
    #pragma unroll
    for (int h = 0; h < 4; h++) rAll[h] = 1.f / (s[h] + 1e-16f);

    if (cached) {
        for (int i = lane; i < deg; i += 32) {
            float4 e4 = *(float4*)(&see[w][i][0]);
            e4.x = __expf(e4.x - m[0]) * rAll[0];
            e4.y = __expf(e4.y - m[1]) * rAll[1];
            e4.z = __expf(e4.z - m[2]) * rAll[2];
            e4.w = __expf(e4.w - m[3]) * rAll[3];
            *(float4*)(&see[w][i][0]) = e4;
        }
    }
    __syncwarp();

    int h = lane >> 3;
    float mh = m[h];
    float rh = rAll[h];
    float adh = adh4[h];

    // pass 2: 2-edge unroll, dual accumulators (two independent gather chains)
    float4 acc0 = make_float4(0.f, 0.f, 0.f, 0.f);
    float4 acc1 = make_float4(0.f, 0.f, 0.f, 0.f);
    int e = 0;
    for (; e + 1 < deg; e += 2) {
        int sA, sB;
        float wA, wB;
        if (cached) {
            sA = ssrc[w][e];     wA = see[w][e][h];
            sB = ssrc[w][e + 1]; wB = see[w][e + 1][h];
        } else {
            sA = csrc[beg + e];
            sB = csrc[beg + e + 1];
            float aA = __ldg(&as1[sA * 4 + h]);
            float aB = __ldg(&as1[sB * 4 + h]);
            float evA = aA + adh, evB = aB + adh;
            float eeA = evA > 0.f ? evA : 0.2f * evA;
            float eeB = evB > 0.f ? evB : 0.2f * evB;
            wA = __expf(eeA - mh) * rh;
            wB = __expf(eeB - mh) * rh;
        }
        const __half2* hpA = reinterpret_cast<const __half2*>(hs + (size_t)sA * DIM) + lane * 2;
        const __half2* hpB = reinterpret_cast<const __half2*>(hs + (size_t)sB * DIM) + lane * 2;
        __half2 a0 = hpA[0], a1 = hpA[1];
        __half2 b0 = hpB[0], b1 = hpB[1];
        float2 fA0 = __half22float2(a0), fA1 = __half22float2(a1);
        float2 fB0 = __half22float2(b0), fB1 = __half22float2(b1);
        acc0.x += wA * fA0.x; acc0.y += wA * fA0.y;
        acc0.z += wA * fA1.x; acc0.w += wA * fA1.y;
        acc1.x += wB * fB0.x; acc1.y += wB * fB0.y;
        acc1.z += wB * fB1.x; acc1.w += wB * fB1.y;
    }
    if (e < deg) {
        int sA;
        float wA;
        if (cached) {
            sA = ssrc[w][e];
            wA = see[w][e][h];
        } else {
            sA = csrc[beg + e];
            float a = __ldg(&as1[sA * 4 + h]);
            float ev = a + adh;
            float ee = ev > 0.f ? ev : 0.2f * ev;
            wA = __expf(ee - mh) * rh;
        }
        const __half2* hp = reinterpret_cast<const __half2*>(hs + (size_t)sA * DIM) + lane * 2;
        __half2 p0 = hp[0], p1 = hp[1];
        float2 f0 = __half22float2(p0), f1 = __half22float2(p1);
        acc0.x += wA * f0.x; acc0.y += wA * f0.y;
        acc0.z += wA * f1.x; acc0.w += wA * f1.y;
    }
    float4 acc = make_float4(acc0.x + acc1.x, acc0.y + acc1.y,
                             acc0.z + acc1.z, acc0.w + acc1.w);
    float4 b = *(const float4*)(bias + lane * 4);
    acc.x += b.x; acc.y += b.y; acc.z += b.z; acc.w += b.w;
    acc.x = acc.x > 0.f ? acc.x : expm1f(acc.x);
    acc.y = acc.y > 0.f ? acc.y : expm1f(acc.y);
    acc.z = acc.z > 0.f ? acc.z : expm1f(acc.z);
    acc.w = acc.w > 0.f ? acc.w : expm1f(acc.w);
    out[d * 32 + lane] = acc;
}

// ---------------- driver ----------------
extern "C" void kernel_launch(void* const* d_in, const int* in_sizes, int n_in,
                              void* d_out, int out_size) {
    const float* x_food  = (const float*)d_in[0];
    const float* x_nut   = (const float*)d_in[1];
    const float* WsrcFN  = (const float*)d_in[2];
    const float* WdstFN  = (const float*)d_in[3];
    const float* aSrcFN  = (const float*)d_in[4];
    const float* aDstFN  = (const float*)d_in[5];
    const float* biasFN  = (const float*)d_in[6];
    const float* WsrcNF  = (const float*)d_in[7];
    const float* WdstNF  = (const float*)d_in[8];
    const float* aSrcNF  = (const float*)d_in[9];
    const float* aDstNF  = (const float*)d_in[10];
    const float* biasNF  = (const float*)d_in[11];
    const int*   ei_fn   = (const int*)d_in[12];
    const int*   ei_nf   = (const int*)d_in[13];
    float* out = (float*)d_out;

    int NF = in_sizes[0] / DIM;
    int NN = in_sizes[1] / DIM;
    int E  = in_sizes[12] / 2;

    __half *hsA, *hsB, *Whx;
    float *hfood, *hnut, *asA, *adA, *asB, *adB, *as2A, *ad2A, *as2B, *ad2B;
    int *deg, *cur, *bsum, *offA, *offB, *srcA, *srcB;
    cudaGetSymbolAddress((void**)&hsA, g_hsA);
    cudaGetSymbolAddress((void**)&hsB, g_hsB);
    cudaGetSymbolAddress((void**)&Whx, g_Whx);
    cudaGetSymbolAddress((void**)&hfood, g_hfood);
    cudaGetSymbolAddress((void**)&hnut, g_hnut);
    cudaGetSymbolAddress((void**)&asA, g_asA);
    cudaGetSymbolAddress((void**)&adA, g_adA);
    cudaGetSymbolAddress((void**)&asB, g_asB);
    cudaGetSymbolAddress((void**)&adB, g_adB);
    cudaGetSymbolAddress((void**)&as2A, g_as2A);
    cudaGetSymbolAddress((void**)&ad2A, g_ad2A);
    cudaGetSymbolAddress((void**)&as2B, g_as2B);
    cudaGetSymbolAddress((void**)&ad2B, g_ad2B);
    cudaGetSymbolAddress((void**)&deg, g_deg);
    cudaGetSymbolAddress((void**)&cur, g_cur);
    cudaGetSymbolAddress((void**)&bsum, g_bsum);
    cudaGetSymbolAddress((void**)&offA, g_offA);
    cudaGetSymbolAddress((void**)&offB, g_offB);
    cudaGetSymbolAddress((void**)&srcA, g_srcA);
    cudaGetSymbolAddress((void**)&srcB, g_srcB);

    int* degA = deg;
    int* degB = deg + MAXN;
    int* curA = cur;
    int* curB = cur + MAXN;
    int* bsumA = bsum;
    int* bsumB = bsum + 256;

    int warpBlk_NN = (NN + 7) / 8;
    int warpBlk_NF = (NF + 7) / 8;
    int gemmTiles_NF = (NF + 63) / 64;
    int gemmTiles_NN = (NN + 63) / 64;
    const int GEMM_GRID = 296;
    int scanBlkA = (NN + SCANB - 1) / SCANB;
    int scanBlkB = (NF + SCANB - 1) / SCANB;

    static cudaStream_t s1 = nullptr, s2 = nullptr, s3 = nullptr;
    static cudaEvent_t eR, eCW, eG0A, eG0B, eCSR, eB0, eA0, eG1A, eG1B, eB1;
    if (!s1) {
        cudaStreamCreateWithFlags(&s1, cudaStreamNonBlocking);
        cudaStreamCreateWithFlags(&s2, cudaStreamNonBlocking);
        cudaStreamCreateWithFlags(&s3, cudaStreamNonBlocking);
        cudaEventCreateWithFlags(&eR,   cudaEventDisableTiming);
        cudaEventCreateWithFlags(&eCW,  cudaEventDisableTiming);
        cudaEventCreateWithFlags(&eG0A, cudaEventDisableTiming);
        cudaEventCreateWithFlags(&eG0B, cudaEventDisableTiming);
        cudaEventCreateWithFlags(&eCSR, cudaEventDisableTiming);
        cudaEventCreateWithFlags(&eB0,  cudaEventDisableTiming);
        cudaEventCreateWithFlags(&eA0,  cudaEventDisableTiming);
        cudaEventCreateWithFlags(&eG1A, cudaEventDisableTiming);
        cudaEventCreateWithFlags(&eG1B, cudaEventDisableTiming);
        cudaEventCreateWithFlags(&eB1,  cudaEventDisableTiming);
    }

    const __half* Whx_f0 = Whx + 0 * DIM * BCOLS;  // food, layer 0
    const __half* Whx_f1 = Whx + 1 * DIM * BCOLS;  // food, layer 1
    const __half* Whx_n0 = Whx + 2 * DIM * BCOLS;  // nut, layer 0
    const __half* Whx_n1 = Whx + 3 * DIM * BCOLS;  // nut, layer 1
    float* out_food = out;
    float* out_nut  = out + (size_t)NF * DIM;

    // ---- fork ----
    cudaEventRecord(eR, 0);
    cudaStreamWaitEvent(s1, eR, 0);
    cudaStreamWaitEvent(s3, eR, 0);
    cudaStreamWaitEvent(s2, eR, 0);

    // S0: pack extended fp16 weights (uv fold inline), layer-0 food GEMM
    convWxK<<<(4 * DIM * BCOLS + 255) / 256, 256>>>(WsrcFN, WdstFN, aSrcFN, aDstFN,
                                                    WsrcNF, WdstNF, aSrcNF, aDstNF, Whx);
    cudaEventRecord(eCW, 0);
    gemmTC<<<GEMM_GRID, 256>>>(x_food, Whx_f0, hsA, (float4*)asA, (float4*)adB,
                               NF, gemmTiles_NF);
    cudaEventRecord(eG0A, 0);

    // S3: layer-0 nut GEMM (parallel with CSR build)
    cudaStreamWaitEvent(s3, eCW, 0);
    gemmTC<<<GEMM_GRID, 256, 0, s3>>>(x_nut, Whx_n0, hsB, (float4*)asB, (float4*)adA,
                                      NN, gemmTiles_NN);
    cudaEventRecord(eG0B, s3);

    // S1: merged CSR build (both relations, 5 launches)
    hist2K<<<2048, 256, 0, s1>>>(ei_fn, ei_nf, degA, degB, E);
    scanSum2K<<<scanBlkA + scanBlkB, SCANB, 0, s1>>>(degA, bsumA, NN, degB, bsumB, NF, scanBlkA);
    scanApply2K<<<scanBlkA + scanBlkB, SCANB, 0, s1>>>(degA, bsumA, offA, curA, NN,
                                                       degB, bsumB, offB, curB, NF, scanBlkA);
    fill2K<<<2048, 256, 0, s1>>>(ei_fn, ei_nf, curA, curB, srcA, srcB, E);
    sortZ2K<<<(NN + NF + 7) / 8, 256, 0, s1>>>(offA, srcA, NN, offB, srcB, NF, deg);
    cudaEventRecord(eCSR, s1);

    // S2: layer-0 nf agg (asB from gemm0B, adB from gemm0A, hsB, CSR-B) -> hfood
    cudaStreamWaitEvent(s2, eG0A, 0);
    cudaStreamWaitEvent(s2, eG0B, 0);
    cudaStreamWaitEvent(s2, eCSR, 0);
    fusedAggK<<<warpBlk_NF, 256, 0, s2>>>(offB, srcB, (const float4*)asB, asB,
                                          (const float4*)adB, hsB, biasNF,
                                          (float4*)hfood, NF);
    cudaEventRecord(eB0, s2);

    // S0: layer-0 fn agg (asA from gemm0A, adA from gemm0B, hsA, CSR-A) -> hnut
    cudaStreamWaitEvent(0, eCSR, 0);
    cudaStreamWaitEvent(0, eG0B, 0);
    fusedAggK<<<warpBlk_NN, 256>>>(offA, srcA, (const float4*)asA, asA,
                                   (const float4*)adA, hsA, biasFN,
                                   (float4*)hnut, NN);
    cudaEventRecord(eA0, 0);

    // S0: layer-1 food GEMM (hfood -> hsA, as2A, ad2B)
    cudaStreamWaitEvent(0, eB0, 0);
    gemmTC<<<GEMM_GRID, 256>>>(hfood, Whx_f1, hsA, (float4*)as2A, (float4*)ad2B,
                               NF, gemmTiles_NF);
    cudaEventRecord(eG1A, 0);

    // S2: layer-1 nut GEMM (hnut -> hsB, as2B, ad2A)
    cudaStreamWaitEvent(s2, eA0, 0);
    gemmTC<<<GEMM_GRID, 256, 0, s2>>>(hnut, Whx_n1, hsB, (float4*)as2B, (float4*)ad2A,
                                      NN, gemmTiles_NN);
    cudaEventRecord(eG1B, s2);

    // S0: layer-1 fn agg (as2A from gemm1A, ad2A from gemm1B) -> out_nut
    cudaStreamWaitEvent(0, eG1B, 0);
    fusedAggK<<<warpBlk_NN, 256>>>(offA, srcA, (const float4*)as2A, as2A,
                                   (const float4*)ad2A, hsA, biasFN + DIM,
                                   (float4*)out_nut, NN);

    // S2: layer-1 nf agg (as2B from gemm1B, ad2B from gemm1A) -> out_food
    cudaStreamWaitEvent(s2, eG1A, 0);
    fusedAggK<<<warpBlk_NF, 256, 0, s2>>>(offB, srcB, (const float4*)as2B, as2B,
                                          (const float4*)ad2B, hsB, biasNF + DIM,
                                          (float4*)out_food, NF);
    cudaEventRecord(eB1, s2);

    // ---- join ----
    cudaStreamWaitEvent(0, eB1, 0);
}